// round 2
// baseline (speedup 1.0000x reference)
#include <cuda_runtime.h>
#include <cstddef>

#define BB 2
#define TT 2048
#define DD 2048
#define HH 16
#define HDD 128
#define MROWS (BB*TT)   // 4096

// ---------------- scratch (static device globals; no runtime alloc) ----------------
__device__ float g_qkv[(size_t)BB * TT * 3 * DD];   // [B,T,3D]
__device__ float g_q[(size_t)BB * HH * TT * HDD];   // [B,H,T,HD]
__device__ float g_k[(size_t)BB * HH * TT * HDD];
__device__ float g_v[(size_t)BB * HH * TT * HDD];
__device__ float g_attn[(size_t)BB * TT * DD];      // [B,T,D]

// ---------------- fp32 GEMM: C[M,N] = A[M,K] * B[N,K]^T (both row-major) ----------------
__global__ __launch_bounds__(256, 2) void sgemm_nt(
    const float* __restrict__ A, const float* __restrict__ Bm,
    float* __restrict__ C, int M, int N, int K)
{
    __shared__ float As[8][128];
    __shared__ float Bs[8][128];
    const int tid = threadIdx.x;
    const int ty = tid >> 4, tx = tid & 15;
    const int brow = blockIdx.y * 128, bcol = blockIdx.x * 128;
    const int lrow = tid >> 1, lk = (tid & 1) * 4;

    const float* Ag = A + (size_t)(brow + lrow) * K + lk;
    const float* Bg = Bm + (size_t)(bcol + lrow) * K + lk;

    float acc[8][8];
    #pragma unroll
    for (int i = 0; i < 8; i++)
        #pragma unroll
        for (int j = 0; j < 8; j++) acc[i][j] = 0.f;

    for (int kt = 0; kt < K; kt += 8) {
        float4 av = *(const float4*)(Ag + kt);
        float4 bv = *(const float4*)(Bg + kt);
        As[lk + 0][lrow] = av.x; As[lk + 1][lrow] = av.y;
        As[lk + 2][lrow] = av.z; As[lk + 3][lrow] = av.w;
        Bs[lk + 0][lrow] = bv.x; Bs[lk + 1][lrow] = bv.y;
        Bs[lk + 2][lrow] = bv.z; Bs[lk + 3][lrow] = bv.w;
        __syncthreads();
        #pragma unroll
        for (int k = 0; k < 8; k++) {
            float a[8], bq[8];
            *(float4*)(a)     = *(const float4*)&As[k][ty * 8];
            *(float4*)(a + 4) = *(const float4*)&As[k][ty * 8 + 4];
            *(float4*)(bq)     = *(const float4*)&Bs[k][tx * 8];
            *(float4*)(bq + 4) = *(const float4*)&Bs[k][tx * 8 + 4];
            #pragma unroll
            for (int i = 0; i < 8; i++)
                #pragma unroll
                for (int j = 0; j < 8; j++)
                    acc[i][j] = fmaf(a[i], bq[j], acc[i][j]);
        }
        __syncthreads();
    }
    #pragma unroll
    for (int i = 0; i < 8; i++) {
        float* Cr = C + (size_t)(brow + ty * 8 + i) * N + bcol + tx * 8;
        *(float4*)Cr       = make_float4(acc[i][0], acc[i][1], acc[i][2], acc[i][3]);
        *(float4*)(Cr + 4) = make_float4(acc[i][4], acc[i][5], acc[i][6], acc[i][7]);
    }
}

// ---------------- RoPE + split into [B,H,T,HD] ----------------
__global__ void rope_split(const float* __restrict__ qkv,
                           const float* __restrict__ cosT,
                           const float* __restrict__ sinT)
{
    const int idx = blockIdx.x;          // b*T*H + t*H + h
    const int h = idx % HH;
    const int t = (idx / HH) % TT;
    const int b = idx / (HH * TT);
    const int c = threadIdx.x;           // 0..127

    const size_t ibase = ((size_t)(b * TT + t)) * (3 * DD) + h * HDD;
    float qv = qkv[ibase + c];
    float kv = qkv[ibase + DD + c];
    float vv = qkv[ibase + 2 * DD + c];
    float qp = qkv[ibase + (c ^ 64)];
    float kp = qkv[ibase + DD + (c ^ 64)];
    float cs = cosT[t * HDD + c];
    float sn = sinT[t * HDD + c];
    float sgn = (c < 64) ? -1.f : 1.f;

    const size_t obase = (((size_t)(b * HH + h)) * TT + t) * HDD + c;
    g_q[obase] = fmaf(qv, cs, sgn * qp * sn);
    g_k[obase] = fmaf(kv, cs, sgn * kp * sn);
    g_v[obase] = vv;
}

// ---------------- fp32 flash attention, 64x64 tiles ----------------
#define FQ 64
#define FK 64
#define QKS 65   // padded row stride for transposed tiles

#define FLASH_SMEM_FLOATS (HDD*QKS*2 + FK*HDD + FK*QKS)
#define FLASH_SMEM_BYTES  (FLASH_SMEM_FLOATS * 4)

__global__ __launch_bounds__(256, 1) void flash_attn()
{
    extern __shared__ float sm[];
    float* QsT = sm;                       // [HD][65]
    float* KsT = QsT + HDD * QKS;          // [HD][65]
    float* Vs  = KsT + HDD * QKS;          // [64][128]
    float* PsT = Vs + FK * HDD;            // [64][65]

    const int qt = blockIdx.x, h = blockIdx.y, b = blockIdx.z;
    const int tid = threadIdx.x;
    const int ty = tid >> 4, tx = tid & 15;
    const size_t hb = ((size_t)(b * HH + h)) * TT * HDD;

    // load Q tile transposed
    const float* Qg = g_q + hb + (size_t)qt * FQ * HDD;
    for (int i = tid; i < FQ * (HDD / 4); i += 256) {
        int r = i >> 5;              // HD/4 = 32 float4 per row
        int c4 = (i & 31) * 4;
        float4 v = *(const float4*)(Qg + r * HDD + c4);
        QsT[(c4 + 0) * QKS + r] = v.x;
        QsT[(c4 + 1) * QKS + r] = v.y;
        QsT[(c4 + 2) * QKS + r] = v.z;
        QsT[(c4 + 3) * QKS + r] = v.w;
    }

    float o[4][8];
    float m[4], l[4];
    #pragma unroll
    for (int i = 0; i < 4; i++) {
        m[i] = -1e30f; l[i] = 0.f;
        #pragma unroll
        for (int j = 0; j < 8; j++) o[i][j] = 0.f;
    }
    const float scale = 0.08838834764831845f;  // 1/sqrt(128)

    for (int kt = 0; kt <= qt; kt++) {
        __syncthreads();   // prior-iter Vs/PsT consumers done; Q load done (iter 0)
        const float* Kg = g_k + hb + (size_t)kt * FK * HDD;
        const float* Vg = g_v + hb + (size_t)kt * FK * HDD;
        for (int i = tid; i < FK * (HDD / 4); i += 256) {
            int r = i >> 5;
            int c4 = (i & 31) * 4;
            float4 v = *(const float4*)(Kg + r * HDD + c4);
            KsT[(c4 + 0) * QKS + r] = v.x;
            KsT[(c4 + 1) * QKS + r] = v.y;
            KsT[(c4 + 2) * QKS + r] = v.z;
            KsT[(c4 + 3) * QKS + r] = v.w;
            *(float4*)&Vs[r * HDD + c4] = *(const float4*)(Vg + r * HDD + c4);
        }
        __syncthreads();

        // S = Q @ K^T  (4x4 per thread)
        float acc[4][4];
        #pragma unroll
        for (int i = 0; i < 4; i++)
            #pragma unroll
            for (int j = 0; j < 4; j++) acc[i][j] = 0.f;

        #pragma unroll 4
        for (int k = 0; k < HDD; k++) {
            float a[4], bq[4];
            #pragma unroll
            for (int i = 0; i < 4; i++) a[i] = QsT[k * QKS + 4 * ty + i];
            #pragma unroll
            for (int j = 0; j < 4; j++) bq[j] = KsT[k * QKS + 4 * tx + j];
            #pragma unroll
            for (int i = 0; i < 4; i++)
                #pragma unroll
                for (int j = 0; j < 4; j++)
                    acc[i][j] = fmaf(a[i], bq[j], acc[i][j]);
        }

        // scale + causal mask (only diagonal tile needs masking)
        if (kt == qt) {
            #pragma unroll
            for (int i = 0; i < 4; i++) {
                int qr = 4 * ty + i;
                #pragma unroll
                for (int j = 0; j < 4; j++) {
                    int kc = 4 * tx + j;
                    acc[i][j] = (kc <= qr) ? acc[i][j] * scale : -1e30f;
                }
            }
        } else {
            #pragma unroll
            for (int i = 0; i < 4; i++)
                #pragma unroll
                for (int j = 0; j < 4; j++) acc[i][j] *= scale;
        }

        // online softmax: rows 4*ty+i, reduce across the 16 tx lanes
        #pragma unroll
        for (int i = 0; i < 4; i++) {
            float mt = fmaxf(fmaxf(acc[i][0], acc[i][1]), fmaxf(acc[i][2], acc[i][3]));
            #pragma unroll
            for (int off = 8; off >= 1; off >>= 1)
                mt = fmaxf(mt, __shfl_xor_sync(0xffffffffu, mt, off));
            float mnew = fmaxf(m[i], mt);
            float alpha = __expf(m[i] - mnew);
            m[i] = mnew;
            float rs = 0.f;
            #pragma unroll
            for (int j = 0; j < 4; j++) {
                float p = __expf(acc[i][j] - mnew);
                PsT[(4 * tx + j) * QKS + 4 * ty + i] = p;
                rs += p;
            }
            #pragma unroll
            for (int off = 8; off >= 1; off >>= 1)
                rs += __shfl_xor_sync(0xffffffffu, rs, off);
            l[i] = l[i] * alpha + rs;
            #pragma unroll
            for (int j = 0; j < 8; j++) o[i][j] *= alpha;
        }
        __syncthreads();

        // O += P @ V  (rows 4*ty+i, cols 8*tx+j)
        #pragma unroll 2
        for (int kk = 0; kk < FK; kk++) {
            float p[4];
            #pragma unroll
            for (int i = 0; i < 4; i++) p[i] = PsT[kk * QKS + 4 * ty + i];
            float4 v0 = *(const float4*)&Vs[kk * HDD + 8 * tx];
            float4 v1 = *(const float4*)&Vs[kk * HDD + 8 * tx + 4];
            #pragma unroll
            for (int i = 0; i < 4; i++) {
                o[i][0] = fmaf(p[i], v0.x, o[i][0]);
                o[i][1] = fmaf(p[i], v0.y, o[i][1]);
                o[i][2] = fmaf(p[i], v0.z, o[i][2]);
                o[i][3] = fmaf(p[i], v0.w, o[i][3]);
                o[i][4] = fmaf(p[i], v1.x, o[i][4]);
                o[i][5] = fmaf(p[i], v1.y, o[i][5]);
                o[i][6] = fmaf(p[i], v1.z, o[i][6]);
                o[i][7] = fmaf(p[i], v1.w, o[i][7]);
            }
        }
    }

    // epilogue: write to g_attn as [B,T,D] (head-interleaved) with 1/l
    float* Og = g_attn + ((size_t)b * TT + (size_t)qt * FQ) * DD + h * HDD;
    #pragma unroll
    for (int i = 0; i < 4; i++) {
        int r = 4 * ty + i;
        float inv = 1.f / l[i];
        float* row = Og + (size_t)r * DD + 8 * tx;
        *(float4*)row       = make_float4(o[i][0] * inv, o[i][1] * inv, o[i][2] * inv, o[i][3] * inv);
        *(float4*)(row + 4) = make_float4(o[i][4] * inv, o[i][5] * inv, o[i][6] * inv, o[i][7] * inv);
    }
}

// ---------------- launch ----------------
extern "C" void kernel_launch(void* const* d_in, const int* in_sizes, int n_in,
                              void* d_out, int out_size)
{
    const float* x    = (const float*)d_in[0];
    const float* cosT = (const float*)d_in[1];
    const float* sinT = (const float*)d_in[2];
    const float* Wqkv = (const float*)d_in[3];
    const float* Wout = (const float*)d_in[4];
    float* out = (float*)d_out;

    float *qkv_p, *attn_p;
    cudaGetSymbolAddress((void**)&qkv_p, g_qkv);
    cudaGetSymbolAddress((void**)&attn_p, g_attn);

    cudaFuncSetAttribute(flash_attn, cudaFuncAttributeMaxDynamicSharedMemorySize,
                         FLASH_SMEM_BYTES);

    // 1) QKV projection: [4096,2048] @ [6144,2048]^T
    sgemm_nt<<<dim3(3 * DD / 128, MROWS / 128), 256>>>(x, Wqkv, qkv_p, MROWS, 3 * DD, DD);

    // 2) RoPE + head split
    rope_split<<<BB * TT * HH, HDD>>>(qkv_p, cosT, sinT);

    // 3) causal flash attention
    flash_attn<<<dim3(TT / FQ, HH, BB), 256, FLASH_SMEM_BYTES>>>();

    // 4) output projection: [4096,2048] @ [2048,2048]^T
    sgemm_nt<<<dim3(DD / 128, MROWS / 128), 256>>>(attn_p, Wout, out, MROWS, DD, DD);
}

// round 4
// speedup vs baseline: 1.6419x; 1.6419x over previous
#include <cuda_runtime.h>
#include <cuda_bf16.h>
#include <cstdint>
#include <cstddef>

#define BB 2
#define TT 2048
#define DD 2048
#define HH 16
#define HDD 128
#define MROWS (BB*TT)   // 4096

// ---------------- scratch (static device globals; no runtime alloc) ----------------
__device__ float g_qkv[(size_t)BB * TT * 3 * DD];   // [B,T,3D]
__device__ float g_q[(size_t)BB * HH * TT * HDD];   // [B,H,T,HD]
__device__ float g_k[(size_t)BB * HH * TT * HDD];
__device__ float g_v[(size_t)BB * HH * TT * HDD];
__device__ float g_attn[(size_t)BB * TT * DD];      // [B,T,D]

// bf16 hi/lo split scratch
__device__ __nv_bfloat16 g_xhi[(size_t)MROWS * DD];
__device__ __nv_bfloat16 g_xlo[(size_t)MROWS * DD];
__device__ __nv_bfloat16 g_wqh[(size_t)3 * DD * DD];
__device__ __nv_bfloat16 g_wql[(size_t)3 * DD * DD];
__device__ __nv_bfloat16 g_woh[(size_t)DD * DD];
__device__ __nv_bfloat16 g_wol[(size_t)DD * DD];
__device__ __nv_bfloat16 g_ahi[(size_t)MROWS * DD];
__device__ __nv_bfloat16 g_alo[(size_t)MROWS * DD];

// ---------------- PTX helpers (sm_80-era, safe on plain sm_100) ----------------
__device__ __forceinline__ uint32_t smem_u32(const void* p) {
    uint32_t a;
    asm("{ .reg .u64 t; cvta.to.shared.u64 t, %1; cvt.u32.u64 %0, t; }" : "=r"(a) : "l"(p));
    return a;
}
#define CP_ASYNC16(dst, src) \
    asm volatile("cp.async.cg.shared.global [%0], [%1], 16;" :: "r"(dst), "l"(src))
#define CP_COMMIT() asm volatile("cp.async.commit_group;" ::: "memory")
#define CP_WAIT0()  asm volatile("cp.async.wait_group 0;" ::: "memory")
#define CP_WAIT1()  asm volatile("cp.async.wait_group 1;" ::: "memory")

__device__ __forceinline__ void ldmx4(uint32_t* r, uint32_t addr) {
    asm volatile("ldmatrix.sync.aligned.m8n8.x4.shared.b16 {%0,%1,%2,%3}, [%4];"
                 : "=r"(r[0]), "=r"(r[1]), "=r"(r[2]), "=r"(r[3]) : "r"(addr));
}
__device__ __forceinline__ void mma_bf16(float* d, const uint32_t* a, const uint32_t* b) {
    asm volatile(
        "mma.sync.aligned.m16n8k16.row.col.f32.bf16.bf16.f32 "
        "{%0,%1,%2,%3}, {%4,%5,%6,%7}, {%8,%9}, {%0,%1,%2,%3};"
        : "+f"(d[0]), "+f"(d[1]), "+f"(d[2]), "+f"(d[3])
        : "r"(a[0]), "r"(a[1]), "r"(a[2]), "r"(a[3]), "r"(b[0]), "r"(b[1]));
}

// ---------------- fp32 -> bf16 hi/lo split ----------------
__global__ void split_bf16(const float* __restrict__ s,
                           __nv_bfloat16* __restrict__ hi,
                           __nv_bfloat16* __restrict__ lo, int n4)
{
    int i = blockIdx.x * 256 + threadIdx.x;
    if (i >= n4) return;
    float4 v = ((const float4*)s)[i];
    __nv_bfloat16 h0 = __float2bfloat16(v.x), h1 = __float2bfloat16(v.y);
    __nv_bfloat16 h2 = __float2bfloat16(v.z), h3 = __float2bfloat16(v.w);
    __nv_bfloat16 l0 = __float2bfloat16(v.x - __bfloat162float(h0));
    __nv_bfloat16 l1 = __float2bfloat16(v.y - __bfloat162float(h1));
    __nv_bfloat16 l2 = __float2bfloat16(v.z - __bfloat162float(h2));
    __nv_bfloat16 l3 = __float2bfloat16(v.w - __bfloat162float(h3));
    __nv_bfloat162* hp = (__nv_bfloat162*)hi;
    __nv_bfloat162* lp = (__nv_bfloat162*)lo;
    hp[2 * i]     = __nv_bfloat162(h0, h1);
    hp[2 * i + 1] = __nv_bfloat162(h2, h3);
    lp[2 * i]     = __nv_bfloat162(l0, l1);
    lp[2 * i + 1] = __nv_bfloat162(l2, l3);
}

// ---------------- mma.sync bf16-split GEMM: C[M,N] = A[M,K] @ B[N,K]^T ----------------
// 128x128 CTA tile, 8 warps (2x4), warp tile 64x32, K-chunk 32, double-buffered cp.async
#define GK 32
#define SROWB 80                       // smem row stride bytes (40 bf16, conflict-free)
#define TBYTES (128 * SROWB)           // 10240 per tensor tile
#define GEMM_SMEM (8 * TBYTES)         // 81920 (2 bufs x 4 tensors)

__global__ __launch_bounds__(256, 1) void gemm_bf16s(
    const __nv_bfloat16* __restrict__ Ah, const __nv_bfloat16* __restrict__ Al,
    const __nv_bfloat16* __restrict__ Bh, const __nv_bfloat16* __restrict__ Bl,
    float* __restrict__ C, int M, int N, int K)
{
    extern __shared__ char smg[];
    const uint32_t sb = smem_u32(smg);
    const int tid = threadIdx.x;
    const int wid = tid >> 5, lane = tid & 31;
    const int wm = wid >> 2, wn = wid & 3;          // warp 64x32 tile
    const int brow = blockIdx.y * 128, bcol = blockIdx.x * 128;
    const int nch = K / GK;

    const __nv_bfloat16* srcs[4] = { Ah, Al, Bh, Bl };

    auto load_chunk = [&](int c) {
        const uint32_t base = sb + (uint32_t)(c & 1) * 4 * TBYTES;
        const size_t ka = (size_t)c * GK;
        #pragma unroll
        for (int t = 0; t < 4; t++) {
            const __nv_bfloat16* s = srcs[t];
            const int rowbase = (t < 2) ? brow : bcol;
            #pragma unroll
            for (int j = 0; j < 2; j++) {
                int i = tid * 2 + j;                 // 0..511
                int r = i >> 2, ch = i & 3;          // 128 rows x 4 x 16B
                const __nv_bfloat16* g = s + (size_t)(rowbase + r) * K + ka + ch * 8;
                CP_ASYNC16(base + t * TBYTES + r * SROWB + ch * 16, g);
            }
        }
        CP_COMMIT();
    };

    float acc[4][4][4];
    #pragma unroll
    for (int mt = 0; mt < 4; mt++)
        #pragma unroll
        for (int nt = 0; nt < 4; nt++)
            #pragma unroll
            for (int e = 0; e < 4; e++) acc[mt][nt][e] = 0.f;

    // fragment smem addresses (constant per thread, per-chunk base added later)
    const uint32_t a_row = (uint32_t)(wm * 64 + (lane & 15)) * SROWB + (lane >> 4) * 16;
    const uint32_t b_row0 = (uint32_t)(wn * 32 + ((lane >> 4) & 1) * 8 + (lane & 7)) * SROWB
                            + ((lane >> 3) & 1) * 16;   // ntile pair base (pair p adds p*16 rows)

    load_chunk(0);

    for (int c = 0; c < nch; c++) {
        if (c + 1 < nch) { load_chunk(c + 1); CP_WAIT1(); }
        else CP_WAIT0();
        __syncthreads();

        const uint32_t bufb = sb + (uint32_t)(c & 1) * 4 * TBYTES;
        #pragma unroll
        for (int ks = 0; ks < 2; ks++) {
            const uint32_t ko = ks * 32;
            uint32_t ah[4][4], al[4][4];
            #pragma unroll
            for (int mt = 0; mt < 4; mt++) {
                uint32_t addr = bufb + a_row + (uint32_t)(mt * 16) * SROWB + ko;
                ldmx4(ah[mt], addr);                     // Ah tile (tensor 0)
                ldmx4(al[mt], addr + TBYTES);            // Al tile (tensor 1)
            }
            uint32_t bh[4][2], bl[4][2];
            #pragma unroll
            for (int p = 0; p < 2; p++) {                // ntile pairs (0,1),(2,3)
                uint32_t addr = bufb + 2 * TBYTES + b_row0 + (uint32_t)(p * 16) * SROWB + ko;
                uint32_t rh[4], rl[4];
                ldmx4(rh, addr);                         // Bh (tensor 2)
                ldmx4(rl, addr + TBYTES);                // Bl (tensor 3)
                bh[2*p][0] = rh[0]; bh[2*p][1] = rh[1];
                bh[2*p+1][0] = rh[2]; bh[2*p+1][1] = rh[3];
                bl[2*p][0] = rl[0]; bl[2*p][1] = rl[1];
                bl[2*p+1][0] = rl[2]; bl[2*p+1][1] = rl[3];
            }
            #pragma unroll
            for (int mt = 0; mt < 4; mt++)
                #pragma unroll
                for (int nt = 0; nt < 4; nt++) {
                    mma_bf16(acc[mt][nt], ah[mt], bh[nt]);
                    mma_bf16(acc[mt][nt], ah[mt], bl[nt]);
                    mma_bf16(acc[mt][nt], al[mt], bh[nt]);
                }
        }
        __syncthreads();
    }

    // epilogue: m16n8 accum layout — lane=4g+t: rows {g,g+8}, cols {2t,2t+1}
    const int g = lane >> 2, t4 = lane & 3;
    #pragma unroll
    for (int mt = 0; mt < 4; mt++) {
        #pragma unroll
        for (int nt = 0; nt < 4; nt++) {
            int row = brow + wm * 64 + mt * 16 + g;
            int col = bcol + wn * 32 + nt * 8 + 2 * t4;
            float* p0 = C + (size_t)row * N + col;
            float* p1 = C + (size_t)(row + 8) * N + col;
            p0[0] = acc[mt][nt][0]; p0[1] = acc[mt][nt][1];
            p1[0] = acc[mt][nt][2]; p1[1] = acc[mt][nt][3];
        }
    }
}

// ---------------- RoPE + split into [B,H,T,HD] ----------------
__global__ void rope_split(const float* __restrict__ qkv,
                           const float* __restrict__ cosT,
                           const float* __restrict__ sinT)
{
    const int idx = blockIdx.x;          // b*T*H + t*H + h
    const int h = idx % HH;
    const int t = (idx / HH) % TT;
    const int b = idx / (HH * TT);
    const int c = threadIdx.x;           // 0..127

    const size_t ibase = ((size_t)(b * TT + t)) * (3 * DD) + h * HDD;
    float qv = qkv[ibase + c];
    float kv = qkv[ibase + DD + c];
    float vv = qkv[ibase + 2 * DD + c];
    float qp = qkv[ibase + (c ^ 64)];
    float kp = qkv[ibase + DD + (c ^ 64)];
    float cs = cosT[t * HDD + c];
    float sn = sinT[t * HDD + c];
    float sgn = (c < 64) ? -1.f : 1.f;

    const size_t obase = (((size_t)(b * HH + h)) * TT + t) * HDD + c;
    g_q[obase] = fmaf(qv, cs, sgn * qp * sn);
    g_k[obase] = fmaf(kv, cs, sgn * kp * sn);
    g_v[obase] = vv;
}

// ---------------- fp32 flash attention, 64x64 tiles ----------------
#define FQ 64
#define FK 64
#define QKS 65

#define FLASH_SMEM_FLOATS (HDD*QKS*2 + FK*HDD + FK*QKS)
#define FLASH_SMEM_BYTES  (FLASH_SMEM_FLOATS * 4)

__global__ __launch_bounds__(256, 1) void flash_attn()
{
    extern __shared__ float sm[];
    float* QsT = sm;                       // [HD][65]
    float* KsT = QsT + HDD * QKS;          // [HD][65]
    float* Vs  = KsT + HDD * QKS;          // [64][128]
    float* PsT = Vs + FK * HDD;            // [64][65]

    const int qt = blockIdx.x, h = blockIdx.y, b = blockIdx.z;
    const int tid = threadIdx.x;
    const int ty = tid >> 4, tx = tid & 15;
    const size_t hb = ((size_t)(b * HH + h)) * TT * HDD;

    const float* Qg = g_q + hb + (size_t)qt * FQ * HDD;
    for (int i = tid; i < FQ * (HDD / 4); i += 256) {
        int r = i >> 5;
        int c4 = (i & 31) * 4;
        float4 v = *(const float4*)(Qg + r * HDD + c4);
        QsT[(c4 + 0) * QKS + r] = v.x;
        QsT[(c4 + 1) * QKS + r] = v.y;
        QsT[(c4 + 2) * QKS + r] = v.z;
        QsT[(c4 + 3) * QKS + r] = v.w;
    }

    float o[4][8];
    float m[4], l[4];
    #pragma unroll
    for (int i = 0; i < 4; i++) {
        m[i] = -1e30f; l[i] = 0.f;
        #pragma unroll
        for (int j = 0; j < 8; j++) o[i][j] = 0.f;
    }
    const float scale = 0.08838834764831845f;

    for (int kt = 0; kt <= qt; kt++) {
        __syncthreads();
        const float* Kg = g_k + hb + (size_t)kt * FK * HDD;
        const float* Vg = g_v + hb + (size_t)kt * FK * HDD;
        for (int i = tid; i < FK * (HDD / 4); i += 256) {
            int r = i >> 5;
            int c4 = (i & 31) * 4;
            float4 v = *(const float4*)(Kg + r * HDD + c4);
            KsT[(c4 + 0) * QKS + r] = v.x;
            KsT[(c4 + 1) * QKS + r] = v.y;
            KsT[(c4 + 2) * QKS + r] = v.z;
            KsT[(c4 + 3) * QKS + r] = v.w;
            *(float4*)&Vs[r * HDD + c4] = *(const float4*)(Vg + r * HDD + c4);
        }
        __syncthreads();

        float acc[4][4];
        #pragma unroll
        for (int i = 0; i < 4; i++)
            #pragma unroll
            for (int j = 0; j < 4; j++) acc[i][j] = 0.f;

        #pragma unroll 4
        for (int k = 0; k < HDD; k++) {
            float a[4], bq[4];
            #pragma unroll
            for (int i = 0; i < 4; i++) a[i] = QsT[k * QKS + 4 * ty + i];
            #pragma unroll
            for (int j = 0; j < 4; j++) bq[j] = KsT[k * QKS + 4 * tx + j];
            #pragma unroll
            for (int i = 0; i < 4; i++)
                #pragma unroll
                for (int j = 0; j < 4; j++)
                    acc[i][j] = fmaf(a[i], bq[j], acc[i][j]);
        }

        if (kt == qt) {
            #pragma unroll
            for (int i = 0; i < 4; i++) {
                int qr = 4 * ty + i;
                #pragma unroll
                for (int j = 0; j < 4; j++) {
                    int kc = 4 * tx + j;
                    acc[i][j] = (kc <= qr) ? acc[i][j] * scale : -1e30f;
                }
            }
        } else {
            #pragma unroll
            for (int i = 0; i < 4; i++)
                #pragma unroll
                for (int j = 0; j < 4; j++) acc[i][j] *= scale;
        }

        #pragma unroll
        for (int i = 0; i < 4; i++) {
            float mt = fmaxf(fmaxf(acc[i][0], acc[i][1]), fmaxf(acc[i][2], acc[i][3]));
            #pragma unroll
            for (int off = 8; off >= 1; off >>= 1)
                mt = fmaxf(mt, __shfl_xor_sync(0xffffffffu, mt, off));
            float mnew = fmaxf(m[i], mt);
            float alpha = __expf(m[i] - mnew);
            m[i] = mnew;
            float rs = 0.f;
            #pragma unroll
            for (int j = 0; j < 4; j++) {
                float p = __expf(acc[i][j] - mnew);
                PsT[(4 * tx + j) * QKS + 4 * ty + i] = p;
                rs += p;
            }
            #pragma unroll
            for (int off = 8; off >= 1; off >>= 1)
                rs += __shfl_xor_sync(0xffffffffu, rs, off);
            l[i] = l[i] * alpha + rs;
            #pragma unroll
            for (int j = 0; j < 8; j++) o[i][j] *= alpha;
        }
        __syncthreads();

        #pragma unroll 2
        for (int kk = 0; kk < FK; kk++) {
            float p[4];
            #pragma unroll
            for (int i = 0; i < 4; i++) p[i] = PsT[kk * QKS + 4 * ty + i];
            float4 v0 = *(const float4*)&Vs[kk * HDD + 8 * tx];
            float4 v1 = *(const float4*)&Vs[kk * HDD + 8 * tx + 4];
            #pragma unroll
            for (int i = 0; i < 4; i++) {
                o[i][0] = fmaf(p[i], v0.x, o[i][0]);
                o[i][1] = fmaf(p[i], v0.y, o[i][1]);
                o[i][2] = fmaf(p[i], v0.z, o[i][2]);
                o[i][3] = fmaf(p[i], v0.w, o[i][3]);
                o[i][4] = fmaf(p[i], v1.x, o[i][4]);
                o[i][5] = fmaf(p[i], v1.y, o[i][5]);
                o[i][6] = fmaf(p[i], v1.z, o[i][6]);
                o[i][7] = fmaf(p[i], v1.w, o[i][7]);
            }
        }
    }

    float* Og = g_attn + ((size_t)b * TT + (size_t)qt * FQ) * DD + h * HDD;
    #pragma unroll
    for (int i = 0; i < 4; i++) {
        int r = 4 * ty + i;
        float inv = 1.f / l[i];
        float* row = Og + (size_t)r * DD + 8 * tx;
        *(float4*)row       = make_float4(o[i][0] * inv, o[i][1] * inv, o[i][2] * inv, o[i][3] * inv);
        *(float4*)(row + 4) = make_float4(o[i][4] * inv, o[i][5] * inv, o[i][6] * inv, o[i][7] * inv);
    }
}

// ---------------- launch ----------------
extern "C" void kernel_launch(void* const* d_in, const int* in_sizes, int n_in,
                              void* d_out, int out_size)
{
    const float* x    = (const float*)d_in[0];
    const float* cosT = (const float*)d_in[1];
    const float* sinT = (const float*)d_in[2];
    const float* Wqkv = (const float*)d_in[3];
    const float* Wout = (const float*)d_in[4];
    float* out = (float*)d_out;

    float *qkv_p, *attn_p;
    cudaGetSymbolAddress((void**)&qkv_p, g_qkv);
    cudaGetSymbolAddress((void**)&attn_p, g_attn);
    __nv_bfloat16 *xhi, *xlo, *wqh, *wql, *woh, *wol, *ahi, *alo;
    cudaGetSymbolAddress((void**)&xhi, g_xhi);
    cudaGetSymbolAddress((void**)&xlo, g_xlo);
    cudaGetSymbolAddress((void**)&wqh, g_wqh);
    cudaGetSymbolAddress((void**)&wql, g_wql);
    cudaGetSymbolAddress((void**)&woh, g_woh);
    cudaGetSymbolAddress((void**)&wol, g_wol);
    cudaGetSymbolAddress((void**)&ahi, g_ahi);
    cudaGetSymbolAddress((void**)&alo, g_alo);

    cudaFuncSetAttribute(flash_attn, cudaFuncAttributeMaxDynamicSharedMemorySize,
                         FLASH_SMEM_BYTES);
    cudaFuncSetAttribute(gemm_bf16s, cudaFuncAttributeMaxDynamicSharedMemorySize,
                         GEMM_SMEM);

    // 0) bf16 hi/lo splits
    split_bf16<<<(MROWS * DD / 4 + 255) / 256, 256>>>(x, xhi, xlo, MROWS * DD / 4);
    split_bf16<<<(3 * DD * DD / 4 + 255) / 256, 256>>>(Wqkv, wqh, wql, 3 * DD * DD / 4);
    split_bf16<<<(DD * DD / 4 + 255) / 256, 256>>>(Wout, woh, wol, DD * DD / 4);

    // 1) QKV projection on tensor cores (mma.sync bf16 3-term split)
    gemm_bf16s<<<dim3(3 * DD / 128, MROWS / 128), 256, GEMM_SMEM>>>(
        xhi, xlo, wqh, wql, qkv_p, MROWS, 3 * DD, DD);

    // 2) RoPE + head split
    rope_split<<<BB * TT * HH, HDD>>>(qkv_p, cosT, sinT);

    // 3) causal flash attention
    flash_attn<<<dim3(TT / FQ, HH, BB), 256, FLASH_SMEM_BYTES>>>();

    // 4) output projection on tensor cores
    split_bf16<<<(MROWS * DD / 4 + 255) / 256, 256>>>(attn_p, ahi, alo, MROWS * DD / 4);
    gemm_bf16s<<<dim3(DD / 128, MROWS / 128), 256, GEMM_SMEM>>>(
        ahi, alo, woh, wol, out, MROWS, DD, DD);
}

// round 5
// speedup vs baseline: 2.4550x; 1.4953x over previous
#include <cuda_runtime.h>
#include <cuda_bf16.h>
#include <cstdint>
#include <cstddef>

#define BB 2
#define TT 2048
#define DD 2048
#define HH 16
#define HDD 128
#define MROWS (BB*TT)   // 4096

// ---------------- scratch (static device globals; no runtime alloc) ----------------
__device__ float g_qkv[(size_t)BB * TT * 3 * DD];   // [B,T,3D]

// bf16 hi/lo splits
__device__ __nv_bfloat16 g_xhi[(size_t)MROWS * DD];
__device__ __nv_bfloat16 g_xlo[(size_t)MROWS * DD];
__device__ __nv_bfloat16 g_wqh[(size_t)3 * DD * DD];
__device__ __nv_bfloat16 g_wql[(size_t)3 * DD * DD];
__device__ __nv_bfloat16 g_woh[(size_t)DD * DD];
__device__ __nv_bfloat16 g_wol[(size_t)DD * DD];
__device__ __nv_bfloat16 g_ahi[(size_t)MROWS * DD];   // attn out (written by flash)
__device__ __nv_bfloat16 g_alo[(size_t)MROWS * DD];

// q/k/v hi-lo bf16, [B,H,T,HD]
#define QKVN ((size_t)BB * HH * TT * HDD)
__device__ __nv_bfloat16 g_qh[QKVN];
__device__ __nv_bfloat16 g_ql[QKVN];
__device__ __nv_bfloat16 g_kh[QKVN];
__device__ __nv_bfloat16 g_kl[QKVN];
__device__ __nv_bfloat16 g_vh[QKVN];
__device__ __nv_bfloat16 g_vl[QKVN];

// ---------------- PTX helpers (sm_80-era, safe on plain sm_100) ----------------
__device__ __forceinline__ uint32_t smem_u32(const void* p) {
    uint32_t a;
    asm("{ .reg .u64 t; cvta.to.shared.u64 t, %1; cvt.u32.u64 %0, t; }" : "=r"(a) : "l"(p));
    return a;
}
#define CP_ASYNC16(dst, src) \
    asm volatile("cp.async.cg.shared.global [%0], [%1], 16;" :: "r"(dst), "l"(src))
#define CP_COMMIT() asm volatile("cp.async.commit_group;" ::: "memory")
#define CP_WAIT0()  asm volatile("cp.async.wait_group 0;" ::: "memory")
#define CP_WAIT1()  asm volatile("cp.async.wait_group 1;" ::: "memory")

__device__ __forceinline__ void ldmx4(uint32_t* r, uint32_t addr) {
    asm volatile("ldmatrix.sync.aligned.m8n8.x4.shared.b16 {%0,%1,%2,%3}, [%4];"
                 : "=r"(r[0]), "=r"(r[1]), "=r"(r[2]), "=r"(r[3]) : "r"(addr));
}
__device__ __forceinline__ void ldmx2(uint32_t* r, uint32_t addr) {
    asm volatile("ldmatrix.sync.aligned.m8n8.x2.shared.b16 {%0,%1}, [%2];"
                 : "=r"(r[0]), "=r"(r[1]) : "r"(addr));
}
__device__ __forceinline__ void mma_bf16(float* d, const uint32_t* a, const uint32_t* b) {
    asm volatile(
        "mma.sync.aligned.m16n8k16.row.col.f32.bf16.bf16.f32 "
        "{%0,%1,%2,%3}, {%4,%5,%6,%7}, {%8,%9}, {%0,%1,%2,%3};"
        : "+f"(d[0]), "+f"(d[1]), "+f"(d[2]), "+f"(d[3])
        : "r"(a[0]), "r"(a[1]), "r"(a[2]), "r"(a[3]), "r"(b[0]), "r"(b[1]));
}
// pack fp32 pair (p0 -> low, p1 -> high) into bf16x2 hi part + residual lo part
__device__ __forceinline__ void pack_hilo(float p0, float p1, uint32_t& hp, uint32_t& lp) {
    asm("cvt.rn.bf16x2.f32 %0, %1, %2;" : "=r"(hp) : "f"(p1), "f"(p0));
    float h0 = __uint_as_float(hp << 16);
    float h1 = __uint_as_float(hp & 0xFFFF0000u);
    float l0 = p0 - h0, l1 = p1 - h1;
    asm("cvt.rn.bf16x2.f32 %0, %1, %2;" : "=r"(lp) : "f"(l1), "f"(l0));
}

// ---------------- fp32 -> bf16 hi/lo split ----------------
__global__ void split_bf16(const float* __restrict__ s,
                           __nv_bfloat16* __restrict__ hi,
                           __nv_bfloat16* __restrict__ lo, int n4)
{
    int i = blockIdx.x * 256 + threadIdx.x;
    if (i >= n4) return;
    float4 v = ((const float4*)s)[i];
    __nv_bfloat16 h0 = __float2bfloat16(v.x), h1 = __float2bfloat16(v.y);
    __nv_bfloat16 h2 = __float2bfloat16(v.z), h3 = __float2bfloat16(v.w);
    __nv_bfloat16 l0 = __float2bfloat16(v.x - __bfloat162float(h0));
    __nv_bfloat16 l1 = __float2bfloat16(v.y - __bfloat162float(h1));
    __nv_bfloat16 l2 = __float2bfloat16(v.z - __bfloat162float(h2));
    __nv_bfloat16 l3 = __float2bfloat16(v.w - __bfloat162float(h3));
    __nv_bfloat162* hp = (__nv_bfloat162*)hi;
    __nv_bfloat162* lp = (__nv_bfloat162*)lo;
    hp[2 * i]     = __nv_bfloat162(h0, h1);
    hp[2 * i + 1] = __nv_bfloat162(h2, h3);
    lp[2 * i]     = __nv_bfloat162(l0, l1);
    lp[2 * i + 1] = __nv_bfloat162(l2, l3);
}

// ---------------- mma.sync bf16-split GEMM: C[M,N] = A[M,K] @ B[N,K]^T ----------------
#define GK 32
#define SROWB 80
#define TBYTES (128 * SROWB)
#define GEMM_SMEM (8 * TBYTES)         // 81920

__global__ __launch_bounds__(256, 2) void gemm_bf16s(
    const __nv_bfloat16* __restrict__ Ah, const __nv_bfloat16* __restrict__ Al,
    const __nv_bfloat16* __restrict__ Bh, const __nv_bfloat16* __restrict__ Bl,
    float* __restrict__ C, int M, int N, int K)
{
    extern __shared__ char smg[];
    const uint32_t sb = smem_u32(smg);
    const int tid = threadIdx.x;
    const int wid = tid >> 5, lane = tid & 31;
    const int wm = wid >> 2, wn = wid & 3;
    const int brow = blockIdx.y * 128, bcol = blockIdx.x * 128;
    const int nch = K / GK;

    const __nv_bfloat16* srcs[4] = { Ah, Al, Bh, Bl };

    auto load_chunk = [&](int c) {
        const uint32_t base = sb + (uint32_t)(c & 1) * 4 * TBYTES;
        const size_t ka = (size_t)c * GK;
        #pragma unroll
        for (int t = 0; t < 4; t++) {
            const __nv_bfloat16* s = srcs[t];
            const int rowbase = (t < 2) ? brow : bcol;
            #pragma unroll
            for (int j = 0; j < 2; j++) {
                int i = tid * 2 + j;
                int r = i >> 2, ch = i & 3;
                const __nv_bfloat16* g = s + (size_t)(rowbase + r) * K + ka + ch * 8;
                CP_ASYNC16(base + t * TBYTES + r * SROWB + ch * 16, g);
            }
        }
        CP_COMMIT();
    };

    float acc[4][4][4];
    #pragma unroll
    for (int mt = 0; mt < 4; mt++)
        #pragma unroll
        for (int nt = 0; nt < 4; nt++)
            #pragma unroll
            for (int e = 0; e < 4; e++) acc[mt][nt][e] = 0.f;

    const uint32_t a_row = (uint32_t)(wm * 64 + (lane & 15)) * SROWB + (lane >> 4) * 16;
    const uint32_t b_row0 = (uint32_t)(wn * 32 + ((lane >> 4) & 1) * 8 + (lane & 7)) * SROWB
                            + ((lane >> 3) & 1) * 16;

    load_chunk(0);

    for (int c = 0; c < nch; c++) {
        if (c + 1 < nch) { load_chunk(c + 1); CP_WAIT1(); }
        else CP_WAIT0();
        __syncthreads();

        const uint32_t bufb = sb + (uint32_t)(c & 1) * 4 * TBYTES;
        #pragma unroll
        for (int ks = 0; ks < 2; ks++) {
            const uint32_t ko = ks * 32;
            uint32_t ah[4][4], al[4][4];
            #pragma unroll
            for (int mt = 0; mt < 4; mt++) {
                uint32_t addr = bufb + a_row + (uint32_t)(mt * 16) * SROWB + ko;
                ldmx4(ah[mt], addr);
                ldmx4(al[mt], addr + TBYTES);
            }
            uint32_t bh[4][2], bl[4][2];
            #pragma unroll
            for (int p = 0; p < 2; p++) {
                uint32_t addr = bufb + 2 * TBYTES + b_row0 + (uint32_t)(p * 16) * SROWB + ko;
                uint32_t rh[4], rl[4];
                ldmx4(rh, addr);
                ldmx4(rl, addr + TBYTES);
                bh[2*p][0] = rh[0]; bh[2*p][1] = rh[1];
                bh[2*p+1][0] = rh[2]; bh[2*p+1][1] = rh[3];
                bl[2*p][0] = rl[0]; bl[2*p][1] = rl[1];
                bl[2*p+1][0] = rl[2]; bl[2*p+1][1] = rl[3];
            }
            #pragma unroll
            for (int mt = 0; mt < 4; mt++)
                #pragma unroll
                for (int nt = 0; nt < 4; nt++) {
                    mma_bf16(acc[mt][nt], ah[mt], bh[nt]);
                    mma_bf16(acc[mt][nt], ah[mt], bl[nt]);
                    mma_bf16(acc[mt][nt], al[mt], bh[nt]);
                }
        }
        __syncthreads();
    }

    const int g = lane >> 2, t4 = lane & 3;
    #pragma unroll
    for (int mt = 0; mt < 4; mt++) {
        #pragma unroll
        for (int nt = 0; nt < 4; nt++) {
            int row = brow + wm * 64 + mt * 16 + g;
            int col = bcol + wn * 32 + nt * 8 + 2 * t4;
            float* p0 = C + (size_t)row * N + col;
            float* p1 = C + (size_t)(row + 8) * N + col;
            p0[0] = acc[mt][nt][0]; p0[1] = acc[mt][nt][1];
            p1[0] = acc[mt][nt][2]; p1[1] = acc[mt][nt][3];
        }
    }
}

// ---------------- RoPE + split into bf16 hi/lo [B,H,T,HD]; q pre-scaled ----------------
__global__ void rope_split(const float* __restrict__ qkv,
                           const float* __restrict__ cosT,
                           const float* __restrict__ sinT)
{
    const int idx = blockIdx.x;
    const int h = idx % HH;
    const int t = (idx / HH) % TT;
    const int b = idx / (HH * TT);
    const int c = threadIdx.x;

    const size_t ibase = ((size_t)(b * TT + t)) * (3 * DD) + h * HDD;
    float qv = qkv[ibase + c];
    float kv = qkv[ibase + DD + c];
    float vv = qkv[ibase + 2 * DD + c];
    float qp = qkv[ibase + (c ^ 64)];
    float kp = qkv[ibase + DD + (c ^ 64)];
    float cs = cosT[t * HDD + c];
    float sn = sinT[t * HDD + c];
    float sgn = (c < 64) ? -1.f : 1.f;

    float q = fmaf(qv, cs, sgn * qp * sn) * 0.08838834764831845f;  // fold 1/sqrt(128)
    float k = fmaf(kv, cs, sgn * kp * sn);

    const size_t o = (((size_t)(b * HH + h)) * TT + t) * HDD + c;
    __nv_bfloat16 qh = __float2bfloat16(q);
    __nv_bfloat16 kh = __float2bfloat16(k);
    __nv_bfloat16 vh = __float2bfloat16(vv);
    g_qh[o] = qh; g_ql[o] = __float2bfloat16(q - __bfloat162float(qh));
    g_kh[o] = kh; g_kl[o] = __float2bfloat16(k - __bfloat162float(kh));
    g_vh[o] = vh; g_vl[o] = __float2bfloat16(vv - __bfloat162float(vh));
}

// ---------------- tensor-core flash attention (bf16 hi/lo, 128x64 tiles) ----------------
#define FQ2 128
#define FK2 64
#define QSTR 272
#define KSTR 272
#define VSTR 144
#define SM_QH 0
#define SM_QL (SM_QH + FQ2*QSTR)        // 34816
#define SM_KH (SM_QL + FQ2*QSTR)        // 69632
#define SM_KL (SM_KH + FK2*KSTR)        // 87040
#define SM_VH (SM_KL + FK2*KSTR)        // 104448
#define SM_VL (SM_VH + HDD*VSTR)        // 122880
#define FLASH2_SMEM (SM_VL + HDD*VSTR)  // 141312

__global__ __launch_bounds__(256, 1) void flash_mma()
{
    extern __shared__ char smf[];
    const uint32_t sb = smem_u32(smf);
    const int tid = threadIdx.x;
    const int wid = tid >> 5, lane = tid & 31;
    const int qt = blockIdx.x, h = blockIdx.y, b = blockIdx.z;
    const size_t hb = ((size_t)(b * HH + h)) * TT * HDD;
    const size_t qb = hb + (size_t)qt * FQ2 * HDD;

    // ---- prologue: Q hi/lo into smem (stays resident) ----
    for (int i = tid; i < FQ2 * 16; i += 256) {
        int r = i >> 4, ch = i & 15;
        *(float4*)(smf + SM_QH + r * QSTR + ch * 16) =
            *(const float4*)(g_qh + qb + (size_t)r * HDD + ch * 8);
        *(float4*)(smf + SM_QL + r * QSTR + ch * 16) =
            *(const float4*)(g_ql + qb + (size_t)r * HDD + ch * 8);
    }

    // fragment addresses
    const uint32_t aq  = sb + SM_QH + (uint32_t)(wid * 16 + (lane & 15)) * QSTR + (lane >> 4) * 16;
    const uint32_t ak  = sb + SM_KH + (uint32_t)(lane & 7) * KSTR + ((lane >> 3) & 1) * 16;
    const uint32_t av  = sb + SM_VH + (uint32_t)(lane & 7) * VSTR + ((lane >> 3) & 1) * 16;

    float oacc[16][4];
    #pragma unroll
    for (int i = 0; i < 16; i++)
        #pragma unroll
        for (int e = 0; e < 4; e++) oacc[i][e] = 0.f;
    float mrow[2] = { -1e30f, -1e30f }, lrow[2] = { 0.f, 0.f };

    const int ktmax = 2 * qt + 1;
    for (int kt = 0; kt <= ktmax; kt++) {
        __syncthreads();   // prior compute done with K/V smem (no-op effect on iter 0 for Q: separate region)
        // load K tile (row-major [kk][hd])
        {
            const size_t kb = hb + (size_t)kt * FK2 * HDD;
            for (int i = tid; i < FK2 * 16; i += 256) {
                int r = i >> 4, ch = i & 15;
                *(float4*)(smf + SM_KH + r * KSTR + ch * 16) =
                    *(const float4*)(g_kh + kb + (size_t)r * HDD + ch * 8);
                *(float4*)(smf + SM_KL + r * KSTR + ch * 16) =
                    *(const float4*)(g_kl + kb + (size_t)r * HDD + ch * 8);
            }
            // V transposed into [hd][kk]
            for (int i = tid; i < FK2 * (HDD / 2); i += 256) {
                int kk = i >> 6, hp = i & 63;
                __nv_bfloat162 vh2 = *(const __nv_bfloat162*)(g_vh + kb + (size_t)kk * HDD + 2 * hp);
                __nv_bfloat162 vl2 = *(const __nv_bfloat162*)(g_vl + kb + (size_t)kk * HDD + 2 * hp);
                *(__nv_bfloat16*)(smf + SM_VH + (2 * hp)     * VSTR + kk * 2) = vh2.x;
                *(__nv_bfloat16*)(smf + SM_VH + (2 * hp + 1) * VSTR + kk * 2) = vh2.y;
                *(__nv_bfloat16*)(smf + SM_VL + (2 * hp)     * VSTR + kk * 2) = vl2.x;
                *(__nv_bfloat16*)(smf + SM_VL + (2 * hp + 1) * VSTR + kk * 2) = vl2.y;
            }
        }
        __syncthreads();

        // ---- S = Q @ K^T (scaled; scale folded into Q) ----
        float sacc[8][4];
        #pragma unroll
        for (int nt = 0; nt < 8; nt++)
            #pragma unroll
            for (int e = 0; e < 4; e++) sacc[nt][e] = 0.f;

        #pragma unroll
        for (int ks = 0; ks < 8; ks++) {
            uint32_t qh4[4], ql4[4];
            ldmx4(qh4, aq + ks * 32);
            ldmx4(ql4, aq + (SM_QL - SM_QH) + ks * 32);
            #pragma unroll
            for (int nt = 0; nt < 8; nt++) {
                uint32_t kh2[2], kl2[2];
                uint32_t kaddr = ak + (uint32_t)(nt * 8) * KSTR + ks * 32;
                ldmx2(kh2, kaddr);
                ldmx2(kl2, kaddr + (SM_KL - SM_KH));
                mma_bf16(sacc[nt], qh4, kh2);
                mma_bf16(sacc[nt], qh4, kl2);
                mma_bf16(sacc[nt], ql4, kh2);
            }
        }

        // ---- causal mask (only the two diagonal-adjacent tiles) ----
        if (kt >= 2 * qt) {
            const int qrow0 = qt * FQ2 + wid * 16 + (lane >> 2);
            #pragma unroll
            for (int nt = 0; nt < 8; nt++) {
                int kc = kt * FK2 + nt * 8 + 2 * (lane & 3);
                if (kc     > qrow0)     sacc[nt][0] = -1e30f;
                if (kc + 1 > qrow0)     sacc[nt][1] = -1e30f;
                if (kc     > qrow0 + 8) sacc[nt][2] = -1e30f;
                if (kc + 1 > qrow0 + 8) sacc[nt][3] = -1e30f;
            }
        }

        // ---- online softmax (rows g, g+8; 4-lane groups share a row) ----
        #pragma unroll
        for (int r = 0; r < 2; r++) {
            float mt = -1e30f;
            #pragma unroll
            for (int nt = 0; nt < 8; nt++)
                mt = fmaxf(mt, fmaxf(sacc[nt][2 * r], sacc[nt][2 * r + 1]));
            mt = fmaxf(mt, __shfl_xor_sync(0xffffffffu, mt, 1));
            mt = fmaxf(mt, __shfl_xor_sync(0xffffffffu, mt, 2));
            float mnew = fmaxf(mrow[r], mt);
            float alpha = __expf(mrow[r] - mnew);
            mrow[r] = mnew;
            float rs = 0.f;
            #pragma unroll
            for (int nt = 0; nt < 8; nt++) {
                float p0 = __expf(sacc[nt][2 * r]     - mnew);
                float p1 = __expf(sacc[nt][2 * r + 1] - mnew);
                sacc[nt][2 * r] = p0; sacc[nt][2 * r + 1] = p1;
                rs += p0 + p1;
            }
            rs += __shfl_xor_sync(0xffffffffu, rs, 1);
            rs += __shfl_xor_sync(0xffffffffu, rs, 2);
            lrow[r] = lrow[r] * alpha + rs;
            #pragma unroll
            for (int nt2 = 0; nt2 < 16; nt2++) {
                oacc[nt2][2 * r]     *= alpha;
                oacc[nt2][2 * r + 1] *= alpha;
            }
        }

        // ---- pack P into bf16 hi/lo A-fragments ----
        uint32_t ph[4][4], pl[4][4];
        #pragma unroll
        for (int ks2 = 0; ks2 < 4; ks2++) {
            pack_hilo(sacc[2*ks2][0],   sacc[2*ks2][1],   ph[ks2][0], pl[ks2][0]);
            pack_hilo(sacc[2*ks2][2],   sacc[2*ks2][3],   ph[ks2][1], pl[ks2][1]);
            pack_hilo(sacc[2*ks2+1][0], sacc[2*ks2+1][1], ph[ks2][2], pl[ks2][2]);
            pack_hilo(sacc[2*ks2+1][2], sacc[2*ks2+1][3], ph[ks2][3], pl[ks2][3]);
        }

        // ---- O += P @ V ----
        #pragma unroll
        for (int ks2 = 0; ks2 < 4; ks2++) {
            #pragma unroll
            for (int nt2 = 0; nt2 < 16; nt2++) {
                uint32_t vh2[2], vl2[2];
                uint32_t vaddr = av + (uint32_t)(nt2 * 8) * VSTR + ks2 * 32;
                ldmx2(vh2, vaddr);
                ldmx2(vl2, vaddr + (SM_VL - SM_VH));
                mma_bf16(oacc[nt2], ph[ks2], vh2);
                mma_bf16(oacc[nt2], ph[ks2], vl2);
                mma_bf16(oacc[nt2], pl[ks2], vh2);
            }
        }
    }

    // ---- epilogue: normalize and write bf16 hi/lo out-proj input [B,T,D] ----
    const float inv0 = 1.f / lrow[0], inv1 = 1.f / lrow[1];
    const int row0 = qt * FQ2 + wid * 16 + (lane >> 2);
    #pragma unroll
    for (int nt2 = 0; nt2 < 16; nt2++) {
        int col = h * HDD + nt2 * 8 + 2 * (lane & 3);
        size_t i0 = (size_t)(b * TT + row0) * DD + col;
        size_t i1 = (size_t)(b * TT + row0 + 8) * DD + col;
        uint32_t hp, lp;
        pack_hilo(oacc[nt2][0] * inv0, oacc[nt2][1] * inv0, hp, lp);
        *(uint32_t*)&g_ahi[i0] = hp; *(uint32_t*)&g_alo[i0] = lp;
        pack_hilo(oacc[nt2][2] * inv1, oacc[nt2][3] * inv1, hp, lp);
        *(uint32_t*)&g_ahi[i1] = hp; *(uint32_t*)&g_alo[i1] = lp;
    }
}

// ---------------- launch ----------------
extern "C" void kernel_launch(void* const* d_in, const int* in_sizes, int n_in,
                              void* d_out, int out_size)
{
    const float* x    = (const float*)d_in[0];
    const float* cosT = (const float*)d_in[1];
    const float* sinT = (const float*)d_in[2];
    const float* Wqkv = (const float*)d_in[3];
    const float* Wout = (const float*)d_in[4];
    float* out = (float*)d_out;

    float* qkv_p;
    cudaGetSymbolAddress((void**)&qkv_p, g_qkv);
    __nv_bfloat16 *xhi, *xlo, *wqh, *wql, *woh, *wol, *ahi, *alo;
    cudaGetSymbolAddress((void**)&xhi, g_xhi);
    cudaGetSymbolAddress((void**)&xlo, g_xlo);
    cudaGetSymbolAddress((void**)&wqh, g_wqh);
    cudaGetSymbolAddress((void**)&wql, g_wql);
    cudaGetSymbolAddress((void**)&woh, g_woh);
    cudaGetSymbolAddress((void**)&wol, g_wol);
    cudaGetSymbolAddress((void**)&ahi, g_ahi);
    cudaGetSymbolAddress((void**)&alo, g_alo);

    cudaFuncSetAttribute(gemm_bf16s, cudaFuncAttributeMaxDynamicSharedMemorySize, GEMM_SMEM);
    cudaFuncSetAttribute(flash_mma, cudaFuncAttributeMaxDynamicSharedMemorySize, FLASH2_SMEM);

    // 0) bf16 hi/lo splits of x and weights
    split_bf16<<<(MROWS * DD / 4 + 255) / 256, 256>>>(x, xhi, xlo, MROWS * DD / 4);
    split_bf16<<<(3 * DD * DD / 4 + 255) / 256, 256>>>(Wqkv, wqh, wql, 3 * DD * DD / 4);
    split_bf16<<<(DD * DD / 4 + 255) / 256, 256>>>(Wout, woh, wol, DD * DD / 4);

    // 1) QKV projection (tensor cores)
    gemm_bf16s<<<dim3(3 * DD / 128, MROWS / 128), 256, GEMM_SMEM>>>(
        xhi, xlo, wqh, wql, qkv_p, MROWS, 3 * DD, DD);

    // 2) RoPE + bf16 hi/lo split of q,k,v
    rope_split<<<BB * TT * HH, HDD>>>(qkv_p, cosT, sinT);

    // 3) causal flash attention (tensor cores), writes g_ahi/g_alo
    flash_mma<<<dim3(TT / FQ2, HH, BB), 256, FLASH2_SMEM>>>();

    // 4) output projection (tensor cores)
    gemm_bf16s<<<dim3(DD / 128, MROWS / 128), 256, GEMM_SMEM>>>(
        ahi, alo, woh, wol, out, MROWS, DD, DD);
}

// round 6
// speedup vs baseline: 2.9514x; 1.2022x over previous
#include <cuda_runtime.h>
#include <cuda_bf16.h>
#include <cstdint>
#include <cstddef>

#define BB 2
#define TT 2048
#define DD 2048
#define HH 16
#define HDD 128
#define MROWS (BB*TT)   // 4096

// ---------------- scratch (static device globals; no runtime alloc) ----------------
__device__ float g_qkv[(size_t)BB * TT * 3 * DD];   // [B,T,3D]

// bf16 hi/lo splits
__device__ __nv_bfloat16 g_xhi[(size_t)MROWS * DD];
__device__ __nv_bfloat16 g_xlo[(size_t)MROWS * DD];
__device__ __nv_bfloat16 g_wqh[(size_t)3 * DD * DD];
__device__ __nv_bfloat16 g_wql[(size_t)3 * DD * DD];
__device__ __nv_bfloat16 g_woh[(size_t)DD * DD];
__device__ __nv_bfloat16 g_wol[(size_t)DD * DD];
__device__ __nv_bfloat16 g_ahi[(size_t)MROWS * DD];   // attn out (written by flash)
__device__ __nv_bfloat16 g_alo[(size_t)MROWS * DD];

// q/k/v hi-lo bf16, [B,H,T,HD]
#define QKVN ((size_t)BB * HH * TT * HDD)
__device__ __nv_bfloat16 g_qh[QKVN];
__device__ __nv_bfloat16 g_ql[QKVN];
__device__ __nv_bfloat16 g_kh[QKVN];
__device__ __nv_bfloat16 g_kl[QKVN];
__device__ __nv_bfloat16 g_vh[QKVN];
__device__ __nv_bfloat16 g_vl[QKVN];

// ---------------- PTX helpers (sm_80-era, safe on plain sm_100) ----------------
__device__ __forceinline__ uint32_t smem_u32(const void* p) {
    uint32_t a;
    asm("{ .reg .u64 t; cvta.to.shared.u64 t, %1; cvt.u32.u64 %0, t; }" : "=r"(a) : "l"(p));
    return a;
}
#define CP_ASYNC16(dst, src) \
    asm volatile("cp.async.cg.shared.global [%0], [%1], 16;" :: "r"(dst), "l"(src))
#define CP_COMMIT() asm volatile("cp.async.commit_group;" ::: "memory")
#define CP_WAIT0()  asm volatile("cp.async.wait_group 0;" ::: "memory")
#define CP_WAIT1()  asm volatile("cp.async.wait_group 1;" ::: "memory")

__device__ __forceinline__ void ldmx4(uint32_t* r, uint32_t addr) {
    asm volatile("ldmatrix.sync.aligned.m8n8.x4.shared.b16 {%0,%1,%2,%3}, [%4];"
                 : "=r"(r[0]), "=r"(r[1]), "=r"(r[2]), "=r"(r[3]) : "r"(addr));
}
__device__ __forceinline__ void ldmx4t(uint32_t* r, uint32_t addr) {
    asm volatile("ldmatrix.sync.aligned.m8n8.x4.trans.shared.b16 {%0,%1,%2,%3}, [%4];"
                 : "=r"(r[0]), "=r"(r[1]), "=r"(r[2]), "=r"(r[3]) : "r"(addr));
}
__device__ __forceinline__ void mma_bf16(float* d, const uint32_t* a, const uint32_t* b) {
    asm volatile(
        "mma.sync.aligned.m16n8k16.row.col.f32.bf16.bf16.f32 "
        "{%0,%1,%2,%3}, {%4,%5,%6,%7}, {%8,%9}, {%0,%1,%2,%3};"
        : "+f"(d[0]), "+f"(d[1]), "+f"(d[2]), "+f"(d[3])
        : "r"(a[0]), "r"(a[1]), "r"(a[2]), "r"(a[3]), "r"(b[0]), "r"(b[1]));
}
// pack fp32 pair (p0 -> low, p1 -> high) into bf16x2 hi part + residual lo part
__device__ __forceinline__ void pack_hilo(float p0, float p1, uint32_t& hp, uint32_t& lp) {
    asm("cvt.rn.bf16x2.f32 %0, %1, %2;" : "=r"(hp) : "f"(p1), "f"(p0));
    float h0 = __uint_as_float(hp << 16);
    float h1 = __uint_as_float(hp & 0xFFFF0000u);
    float l0 = p0 - h0, l1 = p1 - h1;
    asm("cvt.rn.bf16x2.f32 %0, %1, %2;" : "=r"(lp) : "f"(l1), "f"(l0));
}

// ---------------- fp32 -> bf16 hi/lo split ----------------
__global__ void split_bf16(const float* __restrict__ s,
                           __nv_bfloat16* __restrict__ hi,
                           __nv_bfloat16* __restrict__ lo, int n4)
{
    int i = blockIdx.x * 256 + threadIdx.x;
    if (i >= n4) return;
    float4 v = ((const float4*)s)[i];
    __nv_bfloat16 h0 = __float2bfloat16(v.x), h1 = __float2bfloat16(v.y);
    __nv_bfloat16 h2 = __float2bfloat16(v.z), h3 = __float2bfloat16(v.w);
    __nv_bfloat16 l0 = __float2bfloat16(v.x - __bfloat162float(h0));
    __nv_bfloat16 l1 = __float2bfloat16(v.y - __bfloat162float(h1));
    __nv_bfloat16 l2 = __float2bfloat16(v.z - __bfloat162float(h2));
    __nv_bfloat16 l3 = __float2bfloat16(v.w - __bfloat162float(h3));
    __nv_bfloat162* hp = (__nv_bfloat162*)hi;
    __nv_bfloat162* lp = (__nv_bfloat162*)lo;
    hp[2 * i]     = __nv_bfloat162(h0, h1);
    hp[2 * i + 1] = __nv_bfloat162(h2, h3);
    lp[2 * i]     = __nv_bfloat162(l0, l1);
    lp[2 * i + 1] = __nv_bfloat162(l2, l3);
}

// ---------------- mma.sync bf16-split GEMM: C[M,N] = A[M,K] @ B[N,K]^T ----------------
#define GK 32
#define SROWB 80
#define TBYTES (128 * SROWB)
#define GEMM_SMEM (8 * TBYTES)         // 81920

__global__ __launch_bounds__(256, 2) void gemm_bf16s(
    const __nv_bfloat16* __restrict__ Ah, const __nv_bfloat16* __restrict__ Al,
    const __nv_bfloat16* __restrict__ Bh, const __nv_bfloat16* __restrict__ Bl,
    float* __restrict__ C, int M, int N, int K)
{
    extern __shared__ char smg[];
    const uint32_t sb = smem_u32(smg);
    const int tid = threadIdx.x;
    const int wid = tid >> 5, lane = tid & 31;
    const int wm = wid >> 2, wn = wid & 3;
    const int brow = blockIdx.y * 128, bcol = blockIdx.x * 128;
    const int nch = K / GK;

    const __nv_bfloat16* srcs[4] = { Ah, Al, Bh, Bl };

    auto load_chunk = [&](int c) {
        const uint32_t base = sb + (uint32_t)(c & 1) * 4 * TBYTES;
        const size_t ka = (size_t)c * GK;
        #pragma unroll
        for (int t = 0; t < 4; t++) {
            const __nv_bfloat16* s = srcs[t];
            const int rowbase = (t < 2) ? brow : bcol;
            #pragma unroll
            for (int j = 0; j < 2; j++) {
                int i = tid * 2 + j;
                int r = i >> 2, ch = i & 3;
                const __nv_bfloat16* g = s + (size_t)(rowbase + r) * K + ka + ch * 8;
                CP_ASYNC16(base + t * TBYTES + r * SROWB + ch * 16, g);
            }
        }
        CP_COMMIT();
    };

    float acc[4][4][4];
    #pragma unroll
    for (int mt = 0; mt < 4; mt++)
        #pragma unroll
        for (int nt = 0; nt < 4; nt++)
            #pragma unroll
            for (int e = 0; e < 4; e++) acc[mt][nt][e] = 0.f;

    const uint32_t a_row = (uint32_t)(wm * 64 + (lane & 15)) * SROWB + (lane >> 4) * 16;
    const uint32_t b_row0 = (uint32_t)(wn * 32 + ((lane >> 4) & 1) * 8 + (lane & 7)) * SROWB
                            + ((lane >> 3) & 1) * 16;

    load_chunk(0);

    for (int c = 0; c < nch; c++) {
        if (c + 1 < nch) { load_chunk(c + 1); CP_WAIT1(); }
        else CP_WAIT0();
        __syncthreads();

        const uint32_t bufb = sb + (uint32_t)(c & 1) * 4 * TBYTES;
        #pragma unroll
        for (int ks = 0; ks < 2; ks++) {
            const uint32_t ko = ks * 32;
            uint32_t ah[4][4], al[4][4];
            #pragma unroll
            for (int mt = 0; mt < 4; mt++) {
                uint32_t addr = bufb + a_row + (uint32_t)(mt * 16) * SROWB + ko;
                ldmx4(ah[mt], addr);
                ldmx4(al[mt], addr + TBYTES);
            }
            uint32_t bh[4][2], bl[4][2];
            #pragma unroll
            for (int p = 0; p < 2; p++) {
                uint32_t addr = bufb + 2 * TBYTES + b_row0 + (uint32_t)(p * 16) * SROWB + ko;
                uint32_t rh[4], rl[4];
                ldmx4(rh, addr);
                ldmx4(rl, addr + TBYTES);
                bh[2*p][0] = rh[0]; bh[2*p][1] = rh[1];
                bh[2*p+1][0] = rh[2]; bh[2*p+1][1] = rh[3];
                bl[2*p][0] = rl[0]; bl[2*p][1] = rl[1];
                bl[2*p+1][0] = rl[2]; bl[2*p+1][1] = rl[3];
            }
            #pragma unroll
            for (int mt = 0; mt < 4; mt++)
                #pragma unroll
                for (int nt = 0; nt < 4; nt++) {
                    mma_bf16(acc[mt][nt], ah[mt], bh[nt]);
                    mma_bf16(acc[mt][nt], ah[mt], bl[nt]);
                    mma_bf16(acc[mt][nt], al[mt], bh[nt]);
                }
        }
        __syncthreads();
    }

    const int g = lane >> 2, t4 = lane & 3;
    #pragma unroll
    for (int mt = 0; mt < 4; mt++) {
        #pragma unroll
        for (int nt = 0; nt < 4; nt++) {
            int row = brow + wm * 64 + mt * 16 + g;
            int col = bcol + wn * 32 + nt * 8 + 2 * t4;
            float* p0 = C + (size_t)row * N + col;
            float* p1 = C + (size_t)(row + 8) * N + col;
            p0[0] = acc[mt][nt][0]; p0[1] = acc[mt][nt][1];
            p1[0] = acc[mt][nt][2]; p1[1] = acc[mt][nt][3];
        }
    }
}

// ---------------- RoPE + split into bf16 hi/lo [B,H,T,HD]; q pre-scaled ----------------
__global__ void rope_split(const float* __restrict__ qkv,
                           const float* __restrict__ cosT,
                           const float* __restrict__ sinT)
{
    const int idx = blockIdx.x;
    const int h = idx % HH;
    const int t = (idx / HH) % TT;
    const int b = idx / (HH * TT);
    const int c = threadIdx.x;

    const size_t ibase = ((size_t)(b * TT + t)) * (3 * DD) + h * HDD;
    float qv = qkv[ibase + c];
    float kv = qkv[ibase + DD + c];
    float vv = qkv[ibase + 2 * DD + c];
    float qp = qkv[ibase + (c ^ 64)];
    float kp = qkv[ibase + DD + (c ^ 64)];
    float cs = cosT[t * HDD + c];
    float sn = sinT[t * HDD + c];
    float sgn = (c < 64) ? -1.f : 1.f;

    float q = fmaf(qv, cs, sgn * qp * sn) * 0.08838834764831845f;  // fold 1/sqrt(128)
    float k = fmaf(kv, cs, sgn * kp * sn);

    const size_t o = (((size_t)(b * HH + h)) * TT + t) * HDD + c;
    __nv_bfloat16 qh = __float2bfloat16(q);
    __nv_bfloat16 kh = __float2bfloat16(k);
    __nv_bfloat16 vh = __float2bfloat16(vv);
    g_qh[o] = qh; g_ql[o] = __float2bfloat16(q - __bfloat162float(qh));
    g_kh[o] = kh; g_kl[o] = __float2bfloat16(k - __bfloat162float(kh));
    g_vh[o] = vh; g_vl[o] = __float2bfloat16(vv - __bfloat162float(vh));
}

// ---------------- tensor-core flash attention v2 ----------------
// 128x64 tiles; Q resident in smem; K/V cp.async double-buffered;
// K fragments via ldmatrix.x4; V fragments via ldmatrix.x4.trans (no smem transpose).
#define FQ2 128
#define FK2 64
#define FSTR 272                        // row stride bytes (128 bf16 + 16B pad)
#define SM_QH 0
#define SM_QL (FQ2*FSTR)                // 34816
#define SM_K  (2*FQ2*FSTR)              // 69632 ; + buf*34816 ; lo at +17408
#define SM_V  (SM_K + 2*2*FK2*FSTR)     // 139264 ; same layout
#define KVBUF (2*FK2*FSTR)              // 34816 per buffer (hi+lo)
#define HLOFF (FK2*FSTR)                // 17408 hi->lo offset
#define FLASH2_SMEM (SM_V + 2*KVBUF)    // 208896

__global__ __launch_bounds__(256, 1) void flash_mma()
{
    extern __shared__ char smf[];
    const uint32_t sb = smem_u32(smf);
    const int tid = threadIdx.x;
    const int wid = tid >> 5, lane = tid & 31;
    const int qt = blockIdx.x, h = blockIdx.y, b = blockIdx.z;
    const size_t hb = ((size_t)(b * HH + h)) * TT * HDD;
    const size_t qb = hb + (size_t)qt * FQ2 * HDD;

    auto load_kv = [&](int kt) {
        const uint32_t kbase = sb + SM_K + (uint32_t)(kt & 1) * KVBUF;
        const uint32_t vbase = sb + SM_V + (uint32_t)(kt & 1) * KVBUF;
        const size_t kb = hb + (size_t)kt * FK2 * HDD;
        #pragma unroll
        for (int j = 0; j < 4; j++) {
            int i = tid + j * 256;              // 0..1023
            int r = i >> 4, ch = i & 15;
            size_t goff = kb + (size_t)r * HDD + ch * 8;
            uint32_t soff = (uint32_t)r * FSTR + ch * 16;
            CP_ASYNC16(kbase + soff, g_kh + goff);
            CP_ASYNC16(kbase + HLOFF + soff, g_kl + goff);
            CP_ASYNC16(vbase + soff, g_vh + goff);
            CP_ASYNC16(vbase + HLOFF + soff, g_vl + goff);
        }
        CP_COMMIT();
    };

    // ---- prologue: Q hi/lo via cp.async (resident), then first K/V tile ----
    #pragma unroll
    for (int j = 0; j < 8; j++) {
        int i = tid + j * 256;                  // 0..2047
        int r = i >> 4, ch = i & 15;
        size_t goff = qb + (size_t)r * HDD + ch * 8;
        uint32_t soff = (uint32_t)r * FSTR + ch * 16;
        CP_ASYNC16(sb + SM_QH + soff, g_qh + goff);
        CP_ASYNC16(sb + SM_QL + soff, g_ql + goff);
    }
    CP_COMMIT();
    load_kv(0);

    // fragment base addresses
    const uint32_t aq  = sb + SM_QH + (uint32_t)(wid * 16 + (lane & 15)) * FSTR + (lane >> 4) * 16;
    const uint32_t akr = (uint32_t)((lane & 7) + ((lane >> 4) << 3)) * FSTR + ((lane >> 3) & 1) * 16;
    const uint32_t avr = (uint32_t)((lane & 7) + ((lane >> 3) & 1) * 8) * FSTR + ((lane >> 4) << 3) * 2;

    float oacc[16][4];
    #pragma unroll
    for (int i = 0; i < 16; i++)
        #pragma unroll
        for (int e = 0; e < 4; e++) oacc[i][e] = 0.f;
    float mrow[2] = { -1e30f, -1e30f }, lrow[2] = { 0.f, 0.f };

    const int ktmax = 2 * qt + 1;
    for (int kt = 0; kt <= ktmax; kt++) {
        if (kt < ktmax) { load_kv(kt + 1); CP_WAIT1(); }
        else CP_WAIT0();
        __syncthreads();

        const uint32_t kbase = sb + SM_K + (uint32_t)(kt & 1) * KVBUF;
        const uint32_t vbase = sb + SM_V + (uint32_t)(kt & 1) * KVBUF;

        // ---- S = Q @ K^T (scale folded into Q) ----
        float sacc[8][4];
        #pragma unroll
        for (int nt = 0; nt < 8; nt++)
            #pragma unroll
            for (int e = 0; e < 4; e++) sacc[nt][e] = 0.f;

        #pragma unroll
        for (int ks = 0; ks < 8; ks++) {
            uint32_t qh4[4], ql4[4];
            ldmx4(qh4, aq + ks * 32);
            ldmx4(ql4, aq + (SM_QL - SM_QH) + ks * 32);
            #pragma unroll
            for (int p = 0; p < 4; p++) {
                uint32_t kh4[4], kl4[4];
                uint32_t kaddr = kbase + akr + (uint32_t)(p * 16) * FSTR + ks * 32;
                ldmx4(kh4, kaddr);
                ldmx4(kl4, kaddr + HLOFF);
                mma_bf16(sacc[2*p],   qh4, &kh4[0]);
                mma_bf16(sacc[2*p],   qh4, &kl4[0]);
                mma_bf16(sacc[2*p],   ql4, &kh4[0]);
                mma_bf16(sacc[2*p+1], qh4, &kh4[2]);
                mma_bf16(sacc[2*p+1], qh4, &kl4[2]);
                mma_bf16(sacc[2*p+1], ql4, &kh4[2]);
            }
        }

        // ---- causal mask (only diagonal-adjacent tiles) ----
        if (kt >= 2 * qt) {
            const int qrow0 = qt * FQ2 + wid * 16 + (lane >> 2);
            #pragma unroll
            for (int nt = 0; nt < 8; nt++) {
                int kc = kt * FK2 + nt * 8 + 2 * (lane & 3);
                if (kc     > qrow0)     sacc[nt][0] = -1e30f;
                if (kc + 1 > qrow0)     sacc[nt][1] = -1e30f;
                if (kc     > qrow0 + 8) sacc[nt][2] = -1e30f;
                if (kc + 1 > qrow0 + 8) sacc[nt][3] = -1e30f;
            }
        }

        // ---- online softmax (rows g, g+8; 4-lane groups share a row) ----
        #pragma unroll
        for (int r = 0; r < 2; r++) {
            float mt = -1e30f;
            #pragma unroll
            for (int nt = 0; nt < 8; nt++)
                mt = fmaxf(mt, fmaxf(sacc[nt][2 * r], sacc[nt][2 * r + 1]));
            mt = fmaxf(mt, __shfl_xor_sync(0xffffffffu, mt, 1));
            mt = fmaxf(mt, __shfl_xor_sync(0xffffffffu, mt, 2));
            float mnew = fmaxf(mrow[r], mt);
            float alpha = __expf(mrow[r] - mnew);
            mrow[r] = mnew;
            float rs = 0.f;
            #pragma unroll
            for (int nt = 0; nt < 8; nt++) {
                float p0 = __expf(sacc[nt][2 * r]     - mnew);
                float p1 = __expf(sacc[nt][2 * r + 1] - mnew);
                sacc[nt][2 * r] = p0; sacc[nt][2 * r + 1] = p1;
                rs += p0 + p1;
            }
            rs += __shfl_xor_sync(0xffffffffu, rs, 1);
            rs += __shfl_xor_sync(0xffffffffu, rs, 2);
            lrow[r] = lrow[r] * alpha + rs;
            #pragma unroll
            for (int nt2 = 0; nt2 < 16; nt2++) {
                oacc[nt2][2 * r]     *= alpha;
                oacc[nt2][2 * r + 1] *= alpha;
            }
        }

        // ---- pack P into bf16 hi/lo A-fragments ----
        uint32_t ph[4][4], pl[4][4];
        #pragma unroll
        for (int ks2 = 0; ks2 < 4; ks2++) {
            pack_hilo(sacc[2*ks2][0],   sacc[2*ks2][1],   ph[ks2][0], pl[ks2][0]);
            pack_hilo(sacc[2*ks2][2],   sacc[2*ks2][3],   ph[ks2][1], pl[ks2][1]);
            pack_hilo(sacc[2*ks2+1][0], sacc[2*ks2+1][1], ph[ks2][2], pl[ks2][2]);
            pack_hilo(sacc[2*ks2+1][2], sacc[2*ks2+1][3], ph[ks2][3], pl[ks2][3]);
        }

        // ---- O += P @ V (V fragments via ldmatrix.trans, row-major V) ----
        #pragma unroll
        for (int ks2 = 0; ks2 < 4; ks2++) {
            #pragma unroll
            for (int np = 0; np < 8; np++) {
                uint32_t vh4[4], vl4[4];
                uint32_t vaddr = vbase + avr + (uint32_t)(ks2 * 16) * FSTR + (np * 16) * 2;
                ldmx4t(vh4, vaddr);
                ldmx4t(vl4, vaddr + HLOFF);
                mma_bf16(oacc[2*np],   ph[ks2], &vh4[0]);
                mma_bf16(oacc[2*np],   ph[ks2], &vl4[0]);
                mma_bf16(oacc[2*np],   pl[ks2], &vh4[0]);
                mma_bf16(oacc[2*np+1], ph[ks2], &vh4[2]);
                mma_bf16(oacc[2*np+1], ph[ks2], &vl4[2]);
                mma_bf16(oacc[2*np+1], pl[ks2], &vh4[2]);
            }
        }
        __syncthreads();
    }

    // ---- epilogue: normalize and write bf16 hi/lo out-proj input [B,T,D] ----
    const float inv0 = 1.f / lrow[0], inv1 = 1.f / lrow[1];
    const int row0 = qt * FQ2 + wid * 16 + (lane >> 2);
    #pragma unroll
    for (int nt2 = 0; nt2 < 16; nt2++) {
        int col = h * HDD + nt2 * 8 + 2 * (lane & 3);
        size_t i0 = (size_t)(b * TT + row0) * DD + col;
        size_t i1 = (size_t)(b * TT + row0 + 8) * DD + col;
        uint32_t hp, lp;
        pack_hilo(oacc[nt2][0] * inv0, oacc[nt2][1] * inv0, hp, lp);
        *(uint32_t*)&g_ahi[i0] = hp; *(uint32_t*)&g_alo[i0] = lp;
        pack_hilo(oacc[nt2][2] * inv1, oacc[nt2][3] * inv1, hp, lp);
        *(uint32_t*)&g_ahi[i1] = hp; *(uint32_t*)&g_alo[i1] = lp;
    }
}

// ---------------- launch ----------------
extern "C" void kernel_launch(void* const* d_in, const int* in_sizes, int n_in,
                              void* d_out, int out_size)
{
    const float* x    = (const float*)d_in[0];
    const float* cosT = (const float*)d_in[1];
    const float* sinT = (const float*)d_in[2];
    const float* Wqkv = (const float*)d_in[3];
    const float* Wout = (const float*)d_in[4];
    float* out = (float*)d_out;

    float* qkv_p;
    cudaGetSymbolAddress((void**)&qkv_p, g_qkv);
    __nv_bfloat16 *xhi, *xlo, *wqh, *wql, *woh, *wol, *ahi, *alo;
    cudaGetSymbolAddress((void**)&xhi, g_xhi);
    cudaGetSymbolAddress((void**)&xlo, g_xlo);
    cudaGetSymbolAddress((void**)&wqh, g_wqh);
    cudaGetSymbolAddress((void**)&wql, g_wql);
    cudaGetSymbolAddress((void**)&woh, g_woh);
    cudaGetSymbolAddress((void**)&wol, g_wol);
    cudaGetSymbolAddress((void**)&ahi, g_ahi);
    cudaGetSymbolAddress((void**)&alo, g_alo);

    cudaFuncSetAttribute(gemm_bf16s, cudaFuncAttributeMaxDynamicSharedMemorySize, GEMM_SMEM);
    cudaFuncSetAttribute(flash_mma, cudaFuncAttributeMaxDynamicSharedMemorySize, FLASH2_SMEM);

    // 0) bf16 hi/lo splits of x and weights
    split_bf16<<<(MROWS * DD / 4 + 255) / 256, 256>>>(x, xhi, xlo, MROWS * DD / 4);
    split_bf16<<<(3 * DD * DD / 4 + 255) / 256, 256>>>(Wqkv, wqh, wql, 3 * DD * DD / 4);
    split_bf16<<<(DD * DD / 4 + 255) / 256, 256>>>(Wout, woh, wol, DD * DD / 4);

    // 1) QKV projection (tensor cores)
    gemm_bf16s<<<dim3(3 * DD / 128, MROWS / 128), 256, GEMM_SMEM>>>(
        xhi, xlo, wqh, wql, qkv_p, MROWS, 3 * DD, DD);

    // 2) RoPE + bf16 hi/lo split of q,k,v
    rope_split<<<BB * TT * HH, HDD>>>(qkv_p, cosT, sinT);

    // 3) causal flash attention (tensor cores), writes g_ahi/g_alo
    flash_mma<<<dim3(TT / FQ2, HH, BB), 256, FLASH2_SMEM>>>();

    // 4) output projection (tensor cores)
    gemm_bf16s<<<dim3(DD / 128, MROWS / 128), 256, GEMM_SMEM>>>(
        ahi, alo, woh, wol, out, MROWS, DD, DD);
}

// round 7
// speedup vs baseline: 3.1082x; 1.0531x over previous
#include <cuda_runtime.h>
#include <cuda_bf16.h>
#include <cstdint>
#include <cstddef>

#define BB 2
#define TT 2048
#define DD 2048
#define HH 16
#define HDD 128
#define MROWS (BB*TT)   // 4096

// ---------------- scratch (static device globals; no runtime alloc) ----------------
__device__ float g_qkv[(size_t)BB * TT * 3 * DD];   // [B,T,3D]

// bf16 hi/lo splits
__device__ __nv_bfloat16 g_xhi[(size_t)MROWS * DD];
__device__ __nv_bfloat16 g_xlo[(size_t)MROWS * DD];
__device__ __nv_bfloat16 g_wqh[(size_t)3 * DD * DD];
__device__ __nv_bfloat16 g_wql[(size_t)3 * DD * DD];
__device__ __nv_bfloat16 g_woh[(size_t)DD * DD];
__device__ __nv_bfloat16 g_wol[(size_t)DD * DD];
__device__ __nv_bfloat16 g_ahi[(size_t)MROWS * DD];   // attn out (written by flash)
__device__ __nv_bfloat16 g_alo[(size_t)MROWS * DD];

// q/k/v hi-lo bf16, [B,H,T,HD]
#define QKVN ((size_t)BB * HH * TT * HDD)
__device__ __nv_bfloat16 g_qh[QKVN];
__device__ __nv_bfloat16 g_ql[QKVN];
__device__ __nv_bfloat16 g_kh[QKVN];
__device__ __nv_bfloat16 g_kl[QKVN];
__device__ __nv_bfloat16 g_vh[QKVN];
__device__ __nv_bfloat16 g_vl[QKVN];

// ---------------- PTX helpers (sm_80-era, safe on plain sm_100) ----------------
__device__ __forceinline__ uint32_t smem_u32(const void* p) {
    uint32_t a;
    asm("{ .reg .u64 t; cvta.to.shared.u64 t, %1; cvt.u32.u64 %0, t; }" : "=r"(a) : "l"(p));
    return a;
}
#define CP_ASYNC16(dst, src) \
    asm volatile("cp.async.cg.shared.global [%0], [%1], 16;" :: "r"(dst), "l"(src))
#define CP_COMMIT() asm volatile("cp.async.commit_group;" ::: "memory")
#define CP_WAIT0()  asm volatile("cp.async.wait_group 0;" ::: "memory")
#define CP_WAIT1()  asm volatile("cp.async.wait_group 1;" ::: "memory")

__device__ __forceinline__ void ldmx4(uint32_t* r, uint32_t addr) {
    asm volatile("ldmatrix.sync.aligned.m8n8.x4.shared.b16 {%0,%1,%2,%3}, [%4];"
                 : "=r"(r[0]), "=r"(r[1]), "=r"(r[2]), "=r"(r[3]) : "r"(addr));
}
__device__ __forceinline__ void ldmx4t(uint32_t* r, uint32_t addr) {
    asm volatile("ldmatrix.sync.aligned.m8n8.x4.trans.shared.b16 {%0,%1,%2,%3}, [%4];"
                 : "=r"(r[0]), "=r"(r[1]), "=r"(r[2]), "=r"(r[3]) : "r"(addr));
}
__device__ __forceinline__ void mma_bf16(float* d, const uint32_t* a, const uint32_t* b) {
    asm volatile(
        "mma.sync.aligned.m16n8k16.row.col.f32.bf16.bf16.f32 "
        "{%0,%1,%2,%3}, {%4,%5,%6,%7}, {%8,%9}, {%0,%1,%2,%3};"
        : "+f"(d[0]), "+f"(d[1]), "+f"(d[2]), "+f"(d[3])
        : "r"(a[0]), "r"(a[1]), "r"(a[2]), "r"(a[3]), "r"(b[0]), "r"(b[1]));
}
// pack fp32 pair (p0 -> low, p1 -> high) into bf16x2 hi part + residual lo part
__device__ __forceinline__ void pack_hilo(float p0, float p1, uint32_t& hp, uint32_t& lp) {
    asm("cvt.rn.bf16x2.f32 %0, %1, %2;" : "=r"(hp) : "f"(p1), "f"(p0));
    float h0 = __uint_as_float(hp << 16);
    float h1 = __uint_as_float(hp & 0xFFFF0000u);
    float l0 = p0 - h0, l1 = p1 - h1;
    asm("cvt.rn.bf16x2.f32 %0, %1, %2;" : "=r"(lp) : "f"(l1), "f"(l0));
}

// ---------------- fp32 -> bf16 hi/lo split ----------------
__global__ void split_bf16(const float* __restrict__ s,
                           __nv_bfloat16* __restrict__ hi,
                           __nv_bfloat16* __restrict__ lo, int n4)
{
    int i = blockIdx.x * 256 + threadIdx.x;
    if (i >= n4) return;
    float4 v = ((const float4*)s)[i];
    __nv_bfloat16 h0 = __float2bfloat16(v.x), h1 = __float2bfloat16(v.y);
    __nv_bfloat16 h2 = __float2bfloat16(v.z), h3 = __float2bfloat16(v.w);
    __nv_bfloat16 l0 = __float2bfloat16(v.x - __bfloat162float(h0));
    __nv_bfloat16 l1 = __float2bfloat16(v.y - __bfloat162float(h1));
    __nv_bfloat16 l2 = __float2bfloat16(v.z - __bfloat162float(h2));
    __nv_bfloat16 l3 = __float2bfloat16(v.w - __bfloat162float(h3));
    __nv_bfloat162* hp = (__nv_bfloat162*)hi;
    __nv_bfloat162* lp = (__nv_bfloat162*)lo;
    hp[2 * i]     = __nv_bfloat162(h0, h1);
    hp[2 * i + 1] = __nv_bfloat162(h2, h3);
    lp[2 * i]     = __nv_bfloat162(l0, l1);
    lp[2 * i + 1] = __nv_bfloat162(l2, l3);
}

// ---------------- mma.sync bf16-split GEMM: C[M,N] = A[M,K] @ B[N,K]^T ----------------
#define GK 32
#define SROWB 80
#define TBYTES (128 * SROWB)
#define GEMM_SMEM (8 * TBYTES)         // 81920

__global__ __launch_bounds__(256, 2) void gemm_bf16s(
    const __nv_bfloat16* __restrict__ Ah, const __nv_bfloat16* __restrict__ Al,
    const __nv_bfloat16* __restrict__ Bh, const __nv_bfloat16* __restrict__ Bl,
    float* __restrict__ C, int M, int N, int K)
{
    extern __shared__ char smg[];
    const uint32_t sb = smem_u32(smg);
    const int tid = threadIdx.x;
    const int wid = tid >> 5, lane = tid & 31;
    const int wm = wid >> 2, wn = wid & 3;
    const int brow = blockIdx.y * 128, bcol = blockIdx.x * 128;
    const int nch = K / GK;

    const __nv_bfloat16* srcs[4] = { Ah, Al, Bh, Bl };

    auto load_chunk = [&](int c) {
        const uint32_t base = sb + (uint32_t)(c & 1) * 4 * TBYTES;
        const size_t ka = (size_t)c * GK;
        #pragma unroll
        for (int t = 0; t < 4; t++) {
            const __nv_bfloat16* s = srcs[t];
            const int rowbase = (t < 2) ? brow : bcol;
            #pragma unroll
            for (int j = 0; j < 2; j++) {
                int i = tid * 2 + j;
                int r = i >> 2, ch = i & 3;
                const __nv_bfloat16* g = s + (size_t)(rowbase + r) * K + ka + ch * 8;
                CP_ASYNC16(base + t * TBYTES + r * SROWB + ch * 16, g);
            }
        }
        CP_COMMIT();
    };

    float acc[4][4][4];
    #pragma unroll
    for (int mt = 0; mt < 4; mt++)
        #pragma unroll
        for (int nt = 0; nt < 4; nt++)
            #pragma unroll
            for (int e = 0; e < 4; e++) acc[mt][nt][e] = 0.f;

    const uint32_t a_row = (uint32_t)(wm * 64 + (lane & 15)) * SROWB + (lane >> 4) * 16;
    const uint32_t b_row0 = (uint32_t)(wn * 32 + ((lane >> 4) & 1) * 8 + (lane & 7)) * SROWB
                            + ((lane >> 3) & 1) * 16;

    load_chunk(0);

    for (int c = 0; c < nch; c++) {
        if (c + 1 < nch) { load_chunk(c + 1); CP_WAIT1(); }
        else CP_WAIT0();
        __syncthreads();

        const uint32_t bufb = sb + (uint32_t)(c & 1) * 4 * TBYTES;
        #pragma unroll
        for (int ks = 0; ks < 2; ks++) {
            const uint32_t ko = ks * 32;
            uint32_t ah[4][4], al[4][4];
            #pragma unroll
            for (int mt = 0; mt < 4; mt++) {
                uint32_t addr = bufb + a_row + (uint32_t)(mt * 16) * SROWB + ko;
                ldmx4(ah[mt], addr);
                ldmx4(al[mt], addr + TBYTES);
            }
            uint32_t bh[4][2], bl[4][2];
            #pragma unroll
            for (int p = 0; p < 2; p++) {
                uint32_t addr = bufb + 2 * TBYTES + b_row0 + (uint32_t)(p * 16) * SROWB + ko;
                uint32_t rh[4], rl[4];
                ldmx4(rh, addr);
                ldmx4(rl, addr + TBYTES);
                bh[2*p][0] = rh[0]; bh[2*p][1] = rh[1];
                bh[2*p+1][0] = rh[2]; bh[2*p+1][1] = rh[3];
                bl[2*p][0] = rl[0]; bl[2*p][1] = rl[1];
                bl[2*p+1][0] = rl[2]; bl[2*p+1][1] = rl[3];
            }
            #pragma unroll
            for (int mt = 0; mt < 4; mt++)
                #pragma unroll
                for (int nt = 0; nt < 4; nt++) {
                    mma_bf16(acc[mt][nt], ah[mt], bh[nt]);
                    mma_bf16(acc[mt][nt], ah[mt], bl[nt]);
                    mma_bf16(acc[mt][nt], al[mt], bh[nt]);
                }
        }
        __syncthreads();
    }

    const int g = lane >> 2, t4 = lane & 3;
    #pragma unroll
    for (int mt = 0; mt < 4; mt++) {
        #pragma unroll
        for (int nt = 0; nt < 4; nt++) {
            int row = brow + wm * 64 + mt * 16 + g;
            int col = bcol + wn * 32 + nt * 8 + 2 * t4;
            float* p0 = C + (size_t)row * N + col;
            float* p1 = C + (size_t)(row + 8) * N + col;
            p0[0] = acc[mt][nt][0]; p0[1] = acc[mt][nt][1];
            p1[0] = acc[mt][nt][2]; p1[1] = acc[mt][nt][3];
        }
    }
}

// ---------------- RoPE + split into bf16 hi/lo [B,H,T,HD]; q pre-scaled ----------------
__global__ void rope_split(const float* __restrict__ qkv,
                           const float* __restrict__ cosT,
                           const float* __restrict__ sinT)
{
    const int idx = blockIdx.x;
    const int h = idx % HH;
    const int t = (idx / HH) % TT;
    const int b = idx / (HH * TT);
    const int c = threadIdx.x;

    const size_t ibase = ((size_t)(b * TT + t)) * (3 * DD) + h * HDD;
    float qv = qkv[ibase + c];
    float kv = qkv[ibase + DD + c];
    float vv = qkv[ibase + 2 * DD + c];
    float qp = qkv[ibase + (c ^ 64)];
    float kp = qkv[ibase + DD + (c ^ 64)];
    float cs = cosT[t * HDD + c];
    float sn = sinT[t * HDD + c];
    float sgn = (c < 64) ? -1.f : 1.f;

    float q = fmaf(qv, cs, sgn * qp * sn) * 0.08838834764831845f;  // fold 1/sqrt(128)
    float k = fmaf(kv, cs, sgn * kp * sn);

    const size_t o = (((size_t)(b * HH + h)) * TT + t) * HDD + c;
    __nv_bfloat16 qh = __float2bfloat16(q);
    __nv_bfloat16 kh = __float2bfloat16(k);
    __nv_bfloat16 vh = __float2bfloat16(vv);
    g_qh[o] = qh; g_ql[o] = __float2bfloat16(q - __bfloat162float(qh));
    g_kh[o] = kh; g_kl[o] = __float2bfloat16(k - __bfloat162float(kh));
    g_vh[o] = vh; g_vl[o] = __float2bfloat16(vv - __bfloat162float(vh));
}

// ---------------- tensor-core flash attention v2 (longest-first schedule) ----------------
#define FQ2 128
#define FK2 64
#define FSTR 272                        // row stride bytes (128 bf16 + 16B pad)
#define SM_QH 0
#define SM_QL (FQ2*FSTR)                // 34816
#define SM_K  (2*FQ2*FSTR)              // 69632 ; + buf*34816 ; lo at +17408
#define SM_V  (SM_K + 2*2*FK2*FSTR)     // 139264 ; same layout
#define KVBUF (2*FK2*FSTR)              // 34816 per buffer (hi+lo)
#define HLOFF (FK2*FSTR)                // 17408 hi->lo offset
#define FLASH2_SMEM (SM_V + 2*KVBUF)    // 208896

__global__ __launch_bounds__(256, 1) void flash_mma()
{
    extern __shared__ char smf[];
    const uint32_t sb = smem_u32(smf);
    const int tid = threadIdx.x;
    const int wid = tid >> 5, lane = tid & 31;

    // longest-first static schedule: linear index -> (qt desc, h, b)
    const int l = blockIdx.x + 16 * blockIdx.y + 256 * blockIdx.z;   // 0..511
    const int qt = (TT / FQ2 - 1) - (l >> 5);                        // 15..0
    const int bh = l & 31;
    const int h = bh & 15, b = bh >> 4;

    const size_t hb = ((size_t)(b * HH + h)) * TT * HDD;
    const size_t qb = hb + (size_t)qt * FQ2 * HDD;

    auto load_kv = [&](int kt) {
        const uint32_t kbase = sb + SM_K + (uint32_t)(kt & 1) * KVBUF;
        const uint32_t vbase = sb + SM_V + (uint32_t)(kt & 1) * KVBUF;
        const size_t kb = hb + (size_t)kt * FK2 * HDD;
        #pragma unroll
        for (int j = 0; j < 4; j++) {
            int i = tid + j * 256;              // 0..1023
            int r = i >> 4, ch = i & 15;
            size_t goff = kb + (size_t)r * HDD + ch * 8;
            uint32_t soff = (uint32_t)r * FSTR + ch * 16;
            CP_ASYNC16(kbase + soff, g_kh + goff);
            CP_ASYNC16(kbase + HLOFF + soff, g_kl + goff);
            CP_ASYNC16(vbase + soff, g_vh + goff);
            CP_ASYNC16(vbase + HLOFF + soff, g_vl + goff);
        }
        CP_COMMIT();
    };

    // ---- prologue: Q hi/lo via cp.async (resident), then first K/V tile ----
    #pragma unroll
    for (int j = 0; j < 8; j++) {
        int i = tid + j * 256;                  // 0..2047
        int r = i >> 4, ch = i & 15;
        size_t goff = qb + (size_t)r * HDD + ch * 8;
        uint32_t soff = (uint32_t)r * FSTR + ch * 16;
        CP_ASYNC16(sb + SM_QH + soff, g_qh + goff);
        CP_ASYNC16(sb + SM_QL + soff, g_ql + goff);
    }
    CP_COMMIT();
    load_kv(0);

    // fragment base addresses
    const uint32_t aq  = sb + SM_QH + (uint32_t)(wid * 16 + (lane & 15)) * FSTR + (lane >> 4) * 16;
    const uint32_t akr = (uint32_t)((lane & 7) + ((lane >> 4) << 3)) * FSTR + ((lane >> 3) & 1) * 16;
    const uint32_t avr = (uint32_t)((lane & 7) + ((lane >> 3) & 1) * 8) * FSTR + ((lane >> 4) << 3) * 2;

    float oacc[16][4];
    #pragma unroll
    for (int i = 0; i < 16; i++)
        #pragma unroll
        for (int e = 0; e < 4; e++) oacc[i][e] = 0.f;
    float mrow[2] = { -1e30f, -1e30f }, lrow[2] = { 0.f, 0.f };

    const int ktmax = 2 * qt + 1;
    for (int kt = 0; kt <= ktmax; kt++) {
        if (kt < ktmax) { load_kv(kt + 1); CP_WAIT1(); }
        else CP_WAIT0();
        __syncthreads();

        const uint32_t kbase = sb + SM_K + (uint32_t)(kt & 1) * KVBUF;
        const uint32_t vbase = sb + SM_V + (uint32_t)(kt & 1) * KVBUF;

        // ---- S = Q @ K^T (scale folded into Q) ----
        float sacc[8][4];
        #pragma unroll
        for (int nt = 0; nt < 8; nt++)
            #pragma unroll
            for (int e = 0; e < 4; e++) sacc[nt][e] = 0.f;

        #pragma unroll
        for (int ks = 0; ks < 8; ks++) {
            uint32_t qh4[4], ql4[4];
            ldmx4(qh4, aq + ks * 32);
            ldmx4(ql4, aq + (SM_QL - SM_QH) + ks * 32);
            #pragma unroll
            for (int p = 0; p < 4; p++) {
                uint32_t kh4[4], kl4[4];
                uint32_t kaddr = kbase + akr + (uint32_t)(p * 16) * FSTR + ks * 32;
                ldmx4(kh4, kaddr);
                ldmx4(kl4, kaddr + HLOFF);
                mma_bf16(sacc[2*p],   qh4, &kh4[0]);
                mma_bf16(sacc[2*p],   qh4, &kl4[0]);
                mma_bf16(sacc[2*p],   ql4, &kh4[0]);
                mma_bf16(sacc[2*p+1], qh4, &kh4[2]);
                mma_bf16(sacc[2*p+1], qh4, &kl4[2]);
                mma_bf16(sacc[2*p+1], ql4, &kh4[2]);
            }
        }

        // ---- causal mask (only diagonal-adjacent tiles) ----
        if (kt >= 2 * qt) {
            const int qrow0 = qt * FQ2 + wid * 16 + (lane >> 2);
            #pragma unroll
            for (int nt = 0; nt < 8; nt++) {
                int kc = kt * FK2 + nt * 8 + 2 * (lane & 3);
                if (kc     > qrow0)     sacc[nt][0] = -1e30f;
                if (kc + 1 > qrow0)     sacc[nt][1] = -1e30f;
                if (kc     > qrow0 + 8) sacc[nt][2] = -1e30f;
                if (kc + 1 > qrow0 + 8) sacc[nt][3] = -1e30f;
            }
        }

        // ---- online softmax (rows g, g+8; 4-lane groups share a row) ----
        #pragma unroll
        for (int r = 0; r < 2; r++) {
            float mt = -1e30f;
            #pragma unroll
            for (int nt = 0; nt < 8; nt++)
                mt = fmaxf(mt, fmaxf(sacc[nt][2 * r], sacc[nt][2 * r + 1]));
            mt = fmaxf(mt, __shfl_xor_sync(0xffffffffu, mt, 1));
            mt = fmaxf(mt, __shfl_xor_sync(0xffffffffu, mt, 2));
            float mnew = fmaxf(mrow[r], mt);
            float alpha = __expf(mrow[r] - mnew);
            mrow[r] = mnew;
            float rs = 0.f;
            #pragma unroll
            for (int nt = 0; nt < 8; nt++) {
                float p0 = __expf(sacc[nt][2 * r]     - mnew);
                float p1 = __expf(sacc[nt][2 * r + 1] - mnew);
                sacc[nt][2 * r] = p0; sacc[nt][2 * r + 1] = p1;
                rs += p0 + p1;
            }
            rs += __shfl_xor_sync(0xffffffffu, rs, 1);
            rs += __shfl_xor_sync(0xffffffffu, rs, 2);
            lrow[r] = lrow[r] * alpha + rs;
            #pragma unroll
            for (int nt2 = 0; nt2 < 16; nt2++) {
                oacc[nt2][2 * r]     *= alpha;
                oacc[nt2][2 * r + 1] *= alpha;
            }
        }

        // ---- pack P into bf16 hi/lo A-fragments ----
        uint32_t ph[4][4], pl[4][4];
        #pragma unroll
        for (int ks2 = 0; ks2 < 4; ks2++) {
            pack_hilo(sacc[2*ks2][0],   sacc[2*ks2][1],   ph[ks2][0], pl[ks2][0]);
            pack_hilo(sacc[2*ks2][2],   sacc[2*ks2][3],   ph[ks2][1], pl[ks2][1]);
            pack_hilo(sacc[2*ks2+1][0], sacc[2*ks2+1][1], ph[ks2][2], pl[ks2][2]);
            pack_hilo(sacc[2*ks2+1][2], sacc[2*ks2+1][3], ph[ks2][3], pl[ks2][3]);
        }

        // ---- O += P @ V (V fragments via ldmatrix.trans, row-major V) ----
        #pragma unroll
        for (int ks2 = 0; ks2 < 4; ks2++) {
            #pragma unroll
            for (int np = 0; np < 8; np++) {
                uint32_t vh4[4], vl4[4];
                uint32_t vaddr = vbase + avr + (uint32_t)(ks2 * 16) * FSTR + (np * 16) * 2;
                ldmx4t(vh4, vaddr);
                ldmx4t(vl4, vaddr + HLOFF);
                mma_bf16(oacc[2*np],   ph[ks2], &vh4[0]);
                mma_bf16(oacc[2*np],   ph[ks2], &vl4[0]);
                mma_bf16(oacc[2*np],   pl[ks2], &vh4[0]);
                mma_bf16(oacc[2*np+1], ph[ks2], &vh4[2]);
                mma_bf16(oacc[2*np+1], ph[ks2], &vl4[2]);
                mma_bf16(oacc[2*np+1], pl[ks2], &vh4[2]);
            }
        }
        __syncthreads();
    }

    // ---- epilogue: normalize and write bf16 hi/lo out-proj input [B,T,D] ----
    const float inv0 = 1.f / lrow[0], inv1 = 1.f / lrow[1];
    const int row0 = qt * FQ2 + wid * 16 + (lane >> 2);
    #pragma unroll
    for (int nt2 = 0; nt2 < 16; nt2++) {
        int col = h * HDD + nt2 * 8 + 2 * (lane & 3);
        size_t i0 = (size_t)(b * TT + row0) * DD + col;
        size_t i1 = (size_t)(b * TT + row0 + 8) * DD + col;
        uint32_t hp, lp;
        pack_hilo(oacc[nt2][0] * inv0, oacc[nt2][1] * inv0, hp, lp);
        *(uint32_t*)&g_ahi[i0] = hp; *(uint32_t*)&g_alo[i0] = lp;
        pack_hilo(oacc[nt2][2] * inv1, oacc[nt2][3] * inv1, hp, lp);
        *(uint32_t*)&g_ahi[i1] = hp; *(uint32_t*)&g_alo[i1] = lp;
    }
}

// ---------------- launch ----------------
extern "C" void kernel_launch(void* const* d_in, const int* in_sizes, int n_in,
                              void* d_out, int out_size)
{
    const float* x    = (const float*)d_in[0];
    const float* cosT = (const float*)d_in[1];
    const float* sinT = (const float*)d_in[2];
    const float* Wqkv = (const float*)d_in[3];
    const float* Wout = (const float*)d_in[4];
    float* out = (float*)d_out;

    float* qkv_p;
    cudaGetSymbolAddress((void**)&qkv_p, g_qkv);
    __nv_bfloat16 *xhi, *xlo, *wqh, *wql, *woh, *wol, *ahi, *alo;
    cudaGetSymbolAddress((void**)&xhi, g_xhi);
    cudaGetSymbolAddress((void**)&xlo, g_xlo);
    cudaGetSymbolAddress((void**)&wqh, g_wqh);
    cudaGetSymbolAddress((void**)&wql, g_wql);
    cudaGetSymbolAddress((void**)&woh, g_woh);
    cudaGetSymbolAddress((void**)&wol, g_wol);
    cudaGetSymbolAddress((void**)&ahi, g_ahi);
    cudaGetSymbolAddress((void**)&alo, g_alo);

    cudaFuncSetAttribute(gemm_bf16s, cudaFuncAttributeMaxDynamicSharedMemorySize, GEMM_SMEM);
    cudaFuncSetAttribute(flash_mma, cudaFuncAttributeMaxDynamicSharedMemorySize, FLASH2_SMEM);

    // 0) bf16 hi/lo splits of x and weights
    split_bf16<<<(MROWS * DD / 4 + 255) / 256, 256>>>(x, xhi, xlo, MROWS * DD / 4);
    split_bf16<<<(3 * DD * DD / 4 + 255) / 256, 256>>>(Wqkv, wqh, wql, 3 * DD * DD / 4);
    split_bf16<<<(DD * DD / 4 + 255) / 256, 256>>>(Wout, woh, wol, DD * DD / 4);

    // 1) QKV projection (tensor cores)
    gemm_bf16s<<<dim3(3 * DD / 128, MROWS / 128), 256, GEMM_SMEM>>>(
        xhi, xlo, wqh, wql, qkv_p, MROWS, 3 * DD, DD);

    // 2) RoPE + bf16 hi/lo split of q,k,v
    rope_split<<<BB * TT * HH, HDD>>>(qkv_p, cosT, sinT);

    // 3) causal flash attention (tensor cores), writes g_ahi/g_alo
    flash_mma<<<dim3(TT / FQ2, HH, BB), 256, FLASH2_SMEM>>>();

    // 4) output projection (tensor cores)
    gemm_bf16s<<<dim3(DD / 128, MROWS / 128), 256, GEMM_SMEM>>>(
        ahi, alo, woh, wol, out, MROWS, DD, DD);
}